// round 10
// baseline (speedup 1.0000x reference)
#include <cuda_runtime.h>
#include <cuda_fp16.h>
#include <math.h>
#include <stdint.h>

#define BB 2
#define LL 4096
#define EE 1024
#define HH 16
#define DH 64
#define CH 256
#define NCH 16
#define M1 (BB*LL)      // 8192
#define NQKV (3*EE)     // 3072

// ---------------- scratch (static device globals; no allocation) ----------------
__device__ __align__(16) __half g_xh[(size_t)M1*EE];
__device__ __align__(16) __half g_wqkvh[(size_t)NQKV*EE];
__device__ __align__(16) __half g_wouth[(size_t)EE*EE];
__device__ __align__(16) __half g_atth[(size_t)M1*EE];

__device__ __align__(16) __half g_qh[(size_t)BB*HH*LL*DH];
__device__ __align__(16) __half g_kh[(size_t)BB*HH*LL*DH];
__device__ __align__(16) __half g_vh[(size_t)BB*HH*LL*DH];

__device__ float g_G[(size_t)BB*HH*NCH*DH*DH];
__device__ __align__(16) __half g_STh[(size_t)BB*HH*NCH*DH*DH];
__device__ float g_zc[(size_t)BB*HH*NCH*DH];
__device__ float g_Z[(size_t)BB*HH*NCH*DH];

// ---------------- helpers ----------------
__device__ __forceinline__ uint32_t smem_u32(const void* p) {
    uint32_t a;
    asm("{ .reg .u64 t; cvta.to.shared.u64 t, %1; cvt.u32.u64 %0, t; }" : "=r"(a) : "l"(p));
    return a;
}
__device__ __forceinline__ void ldmx4(uint32_t* r, uint32_t a) {
    asm volatile("ldmatrix.sync.aligned.m8n8.x4.shared.b16 {%0,%1,%2,%3}, [%4];"
        : "=r"(r[0]), "=r"(r[1]), "=r"(r[2]), "=r"(r[3]) : "r"(a));
}
__device__ __forceinline__ void mma_f16(float* d, const uint32_t* a, const uint32_t* b) {
    asm volatile(
        "mma.sync.aligned.m16n8k16.row.col.f32.f16.f16.f32 "
        "{%0,%1,%2,%3}, {%4,%5,%6,%7}, {%8,%9}, {%0,%1,%2,%3};"
        : "+f"(d[0]), "+f"(d[1]), "+f"(d[2]), "+f"(d[3])
        : "r"(a[0]), "r"(a[1]), "r"(a[2]), "r"(a[3]), "r"(b[0]), "r"(b[1]));
}
__device__ __forceinline__ uint32_t packh2(float a, float b) {
    __half2 t = __halves2half2(__float2half_rn(a), __float2half_rn(b));
    return *(uint32_t*)&t;
}

#define CP_ASYNC16(s, g) \
    asm volatile("cp.async.cg.shared.global [%0], [%1], 16;" :: "r"(s), "l"(g))
#define CP_COMMIT() asm volatile("cp.async.commit_group;")
#define CP_WAIT1()  asm volatile("cp.async.wait_group 1;")
#define CP_WAIT0()  asm volatile("cp.async.wait_group 0;")

// ---------------- fp32 -> fp16 converter ----------------
template<int W>
__global__ __launch_bounds__(256)
void convert_kernel(const float* __restrict__ src, int n4)
{
    __half* dst = (W == 0) ? g_xh : (W == 1) ? g_wqkvh : g_wouth;
    int i = blockIdx.x * 256 + threadIdx.x;
    if (i >= n4) return;
    float4 v = ((const float4*)src)[i];
    ((__half2*)dst)[i*2 + 0] = __halves2half2(__float2half_rn(v.x), __float2half_rn(v.y));
    ((__half2*)dst)[i*2 + 1] = __halves2half2(__float2half_rn(v.z), __float2half_rn(v.w));
}

// ---------------- fp16 HMMA GEMM, 3-stage cp.async, BK=64 ----------------
// C[M,N] = A[M,K] * B[N,K]^T, fp32 accumulate.
// Block 256x128 (M x N), 8 warps (4m x 2n), warp tile 64x64, 256 threads, 1 CTA/SM.
// MODE 0: A=g_xh, B=g_wqkvh (N=3072), epilogue feature map -> fp16 q/k/v
// MODE 1: A=g_atth, B=g_wouth (N=1024), plain fp32 store to C
#define GP 144
#define ATILE (256*GP)          // 36864
#define BTILE (128*GP)          // 18432
#define GSTAGE (ATILE + BTILE)  // 55296
#define NSTAGE 3
#define KC_N 16                 // 1024 / 64

template<int MODE>
__global__ __launch_bounds__(256, 1)
void hmma_gemm_kernel(float* __restrict__ C)
{
    const __half* __restrict__ A = (MODE == 0) ? g_xh : g_atth;
    const __half* __restrict__ B = (MODE == 0) ? g_wqkvh : g_wouth;

    const int m0 = blockIdx.y * 256;
    const int n0 = blockIdx.x * 128;
    const int tid = threadIdx.x;
    const int wid = tid >> 5;
    const int lane = tid & 31;
    const int wm = (wid >> 1) * 64;   // 0,64,128,192
    const int wn = (wid & 1) * 64;    // 0,64

    extern __shared__ char smc[];
    const uint32_t base = smem_u32(smc);

    float acc[4][8][4];
#pragma unroll
    for (int a = 0; a < 4; a++)
#pragma unroll
        for (int b = 0; b < 8; b++)
#pragma unroll
            for (int c = 0; c < 4; c++) acc[a][b][c] = 0.f;

    const int g = lane >> 3, lr = lane & 7;
    const int a_row  = ((g & 1) << 3) + lr;
    const int a_xtra = (g & 2) ? 16 : 0;
    const int b_row  = ((g >> 1) << 3) + lr;
    const int b_xtra = (g & 1) ? 16 : 0;

    // per-thread fixed slot decomposition for cp.async
    const int pf_row = tid >> 3;      // 0..31
    const int pf_c16 = tid & 7;

    auto prefetch = [&](int kc, int stg) {
        const int kb = kc * 64;
        const uint32_t sb = base + stg * GSTAGE;
        // A: 256 rows x 8 chunks = 2048 slots, 8 passes
#pragma unroll
        for (int i = 0; i < 8; i++) {
            int row = pf_row + i * 32;
            CP_ASYNC16(sb + (uint32_t)(row * GP + pf_c16 * 16),
                       __cvta_generic_to_global(A + (size_t)(m0 + row) * EE + kb + pf_c16 * 8));
        }
        // B: 128 rows x 8 chunks = 1024 slots, 4 passes
#pragma unroll
        for (int i = 0; i < 4; i++) {
            int row = pf_row + i * 32;
            CP_ASYNC16(sb + ATILE + (uint32_t)(row * GP + pf_c16 * 16),
                       __cvta_generic_to_global(B + (size_t)(n0 + row) * EE + kb + pf_c16 * 8));
        }
    };

    prefetch(0, 0); CP_COMMIT();
    prefetch(1, 1); CP_COMMIT();

    int stg = 0;
    for (int kc = 0; kc < KC_N; kc++) {
        if (kc < KC_N - 1) { CP_WAIT1(); } else { CP_WAIT0(); }
        __syncthreads();
        if (kc + 2 < KC_N) {
            int nstg = stg + 2; if (nstg >= NSTAGE) nstg -= NSTAGE;
            prefetch(kc + 2, nstg);
            CP_COMMIT();
        }

        const uint32_t sb = base + stg * GSTAGE;
#pragma unroll
        for (int t = 0; t < 4; t++) {
            uint32_t bf[16];
#pragma unroll
            for (int np = 0; np < 4; np++)
                ldmx4(bf + np*4, sb + ATILE + (uint32_t)((wn + np*16 + b_row) * GP + t*32 + b_xtra));
            uint32_t af[16];
#pragma unroll
            for (int mi = 0; mi < 4; mi++)
                ldmx4(af + mi*4, sb + (uint32_t)((wm + mi*16 + a_row) * GP + t*32 + a_xtra));
#pragma unroll
            for (int mi = 0; mi < 4; mi++)
#pragma unroll
                for (int ni = 0; ni < 8; ni++)
                    mma_f16(acc[mi][ni], af + mi*4, &bf[(ni >> 1)*4 + (ni & 1)*2]);
        }
        if (++stg >= NSTAGE) stg -= NSTAGE;
    }

    // epilogue
#pragma unroll
    for (int mi = 0; mi < 4; mi++) {
        int mrow = m0 + wm + mi*16 + (lane >> 2);
#pragma unroll
        for (int half = 0; half < 2; half++) {
            int m = mrow + half * 8;
#pragma unroll
            for (int ni = 0; ni < 8; ni++) {
                int n = n0 + wn + ni*8 + (lane & 3)*2;
                float v0 = acc[mi][ni][half*2 + 0];
                float v1 = acc[mi][ni][half*2 + 1];
                if (MODE == 1) {
                    *(float2*)(C + (size_t)m * EE + n) = make_float2(v0, v1);
                } else {
                    int s = n >> 10, h = (n >> 6) & 15, d = n & 63;
                    int bidx = m >> 12, l = m & 4095;
                    float r0, r1;
                    if (s == 0) {
                        r0 = (v0 > 0.f ? v0 + 1.f : expf(v0)) * 0.125f;
                        r1 = (v1 > 0.f ? v1 + 1.f : expf(v1)) * 0.125f;
                    } else if (s == 1) {
                        r0 = (v0 > 0.f ? v0 + 1.f : expf(v0));
                        r1 = (v1 > 0.f ? v1 + 1.f : expf(v1));
                    } else {
                        r0 = v0; r1 = v1;
                    }
                    __half* dst = (s == 0) ? g_qh : (s == 1) ? g_kh : g_vh;
                    size_t off = ((size_t)(bidx*HH + h) * LL + l) * DH + d;
                    *(uint32_t*)(dst + off) = packh2(r0, r1);
                }
            }
        }
    }
}

// ---------------- per-chunk Gram: G = K_c^T V_c  (64x64), z = sum K_c ----------------
__global__ __launch_bounds__(256)
void chunk_kv_kernel()
{
    const int c = blockIdx.x, h = blockIdx.y, b = blockIdx.z;
    const int bh = b * HH + h;
    const size_t tokbase = ((size_t)bh * LL + c * CH) * DH;
    const __half* kh = g_kh + tokbase;
    const __half* vh = g_vh + tokbase;

    __shared__ float ks[64][65];
    __shared__ float vs[64][65];

    const int tid = threadIdx.x;
    const int tx = tid & 15, ty = tid >> 4;

    float acc[4][4];
#pragma unroll
    for (int i = 0; i < 4; i++)
#pragma unroll
        for (int j = 0; j < 4; j++) acc[i][j] = 0.f;
    float zacc = 0.f;

    for (int lt = 0; lt < 4; lt++) {
#pragma unroll
        for (int t = 0; t < 4; t++) {
            int idx = tid + t * 256;
            int row = idx >> 4, c4 = idx & 15;
            size_t off = (size_t)(lt*64 + row) * DH + c4 * 4;
            float2 a0 = __half22float2(*(const __half2*)(kh + off));
            float2 a1 = __half22float2(*(const __half2*)(kh + off + 2));
            ks[row][c4*4+0] = a0.x; ks[row][c4*4+1] = a0.y;
            ks[row][c4*4+2] = a1.x; ks[row][c4*4+3] = a1.y;
            float2 b0 = __half22float2(*(const __half2*)(vh + off));
            float2 b1 = __half22float2(*(const __half2*)(vh + off + 2));
            vs[row][c4*4+0] = b0.x; vs[row][c4*4+1] = b0.y;
            vs[row][c4*4+2] = b1.x; vs[row][c4*4+3] = b1.y;
        }
        __syncthreads();
#pragma unroll 8
        for (int l = 0; l < 64; l++) {
            float a[4], bb[4];
#pragma unroll
            for (int i = 0; i < 4; i++) a[i] = ks[l][ty*4 + i];
#pragma unroll
            for (int j = 0; j < 4; j++) bb[j] = vs[l][tx*4 + j];
#pragma unroll
            for (int i = 0; i < 4; i++)
#pragma unroll
                for (int j = 0; j < 4; j++) acc[i][j] += a[i] * bb[j];
        }
        if (tid < 64) {
#pragma unroll 8
            for (int l = 0; l < 64; l++) zacc += ks[l][tid];
        }
        __syncthreads();
    }

    float* Gout = g_G + ((size_t)bh * NCH + c) * DH * DH;
#pragma unroll
    for (int i = 0; i < 4; i++)
#pragma unroll
        for (int j = 0; j < 4; j++)
            Gout[(ty*4 + i) * DH + tx*4 + j] = acc[i][j];
    if (tid < 64) g_zc[((size_t)bh * NCH + c) * DH + tid] = zacc;
}

// ---------------- exclusive prefix over chunks; emits S^T as fp16 ----------------
__global__ __launch_bounds__(256)
void prefix_kernel()
{
    const int bh = blockIdx.x;
    const int tid = threadIdx.x;
    for (int idx = tid; idx < DH*DH; idx += 256) {
        int d = idx >> 6, e = idx & 63;
        float run = 0.f;
        for (int c = 0; c < NCH; c++) {
            size_t gbase = ((size_t)bh * NCH + c) * DH * DH;
            g_STh[gbase + e*DH + d] = __float2half_rn(run);
            run += g_G[gbase + idx];
        }
    }
    if (tid < DH) {
        float run = 0.f;
        for (int c = 0; c < NCH; c++) {
            size_t o = ((size_t)bh * NCH + c) * DH + tid;
            g_Z[o] = run;
            run += g_zc[o];
        }
    }
}

// ---------------- attention core (fp16 HMMA): per (b,h,c), 256x64 tile ----------------
#define AP 144
#define QH_O  0
#define KH_O  36864
#define VT_O  46080
#define ST_O  55296
#define Z_O   64512
#define ATTN_SMEM (Z_O + 256)

__global__ __launch_bounds__(256, 1)
void attn_core_kernel()
{
    const int c = blockIdx.x, h = blockIdx.y, b = blockIdx.z;
    const int bh = b * HH + h;
    const size_t tokbase = (size_t)bh * LL + c * CH;

    extern __shared__ char sm[];
    const uint32_t sbase = smem_u32(sm);

    const int tid = threadIdx.x;
    const int w = tid >> 5;
    const int lane = tid & 31;
    const int g = lane >> 3, lr = lane & 7;
    const int a_row  = ((g & 1) << 3) + lr;
    const int a_xtra = (g & 2) ? 16 : 0;
    const int b_row  = ((g >> 1) << 3) + lr;
    const int b_xtra = (g & 1) ? 16 : 0;

    // load Q (256x64)
    {
        const __half* qh = g_qh + tokbase * DH;
#pragma unroll
        for (int t = 0; t < 8; t++) {
            int idx = tid + t * 256;
            int row = idx >> 3, c16 = idx & 7;
            *(uint4*)(sm + QH_O + row*AP + c16*16) = *(const uint4*)(qh + (size_t)row*DH + c16*8);
        }
    }
    // load S^T (64x64) + Z
    {
        const size_t stb = ((size_t)bh * NCH + c) * DH * DH;
#pragma unroll
        for (int t = 0; t < 2; t++) {
            int idx = tid + t * 256;
            int row = idx >> 3, c16 = idx & 7;
            *(uint4*)(sm + ST_O + row*AP + c16*16) = *(const uint4*)(g_STh + stb + (size_t)row*DH + c16*8);
        }
        if (tid < DH) *(float*)(sm + Z_O + tid*4) = g_Z[((size_t)bh * NCH + c) * DH + tid];
    }

    float num[2][8][4];
#pragma unroll
    for (int mi = 0; mi < 2; mi++)
#pragma unroll
        for (int ni = 0; ni < 8; ni++)
#pragma unroll
            for (int e = 0; e < 4; e++) num[mi][ni][e] = 0.f;
    float den[2][2] = {{0.f, 0.f}, {0.f, 0.f}};

    for (int jb = 0; jb < 4; jb++) {
        __syncthreads();   // strip buffers free (also orders Q/ST loads on jb==0)
        // load K strip (64x64)
        {
            const __half* kh = g_kh + (tokbase + jb*64) * DH;
#pragma unroll
            for (int t = 0; t < 2; t++) {
                int idx = tid + t * 256;
                int row = idx >> 3, c16 = idx & 7;
                *(uint4*)(sm + KH_O + row*AP + c16*16) = *(const uint4*)(kh + (size_t)row*DH + c16*8);
            }
        }
        // load + transpose V strip: Vt[e][m]
        {
            const __half* vh = g_vh + (tokbase + jb*64) * DH;
#pragma unroll
            for (int t = 0; t < 4; t++) {
                int s = tid + t * 256;
                int m = s >> 4, e = (s & 15) * 4;
                __half2 h0 = *(const __half2*)(vh + (size_t)m*DH + e);
                __half2 h1 = *(const __half2*)(vh + (size_t)m*DH + e + 2);
                *(__half*)(sm + VT_O + (e+0)*AP + m*2) = __low2half(h0);
                *(__half*)(sm + VT_O + (e+1)*AP + m*2) = __high2half(h0);
                *(__half*)(sm + VT_O + (e+2)*AP + m*2) = __low2half(h1);
                *(__half*)(sm + VT_O + (e+3)*AP + m*2) = __high2half(h1);
            }
        }
        __syncthreads();

        // GEMM1: P = Q * Kstrip^T  (warp: 32x64, k=64)
        float pacc[2][8][4];
#pragma unroll
        for (int mi = 0; mi < 2; mi++)
#pragma unroll
            for (int ni = 0; ni < 8; ni++)
#pragma unroll
                for (int e = 0; e < 4; e++) pacc[mi][ni][e] = 0.f;

#pragma unroll
        for (int t = 0; t < 4; t++) {
            uint32_t kb[16];
#pragma unroll
            for (int np = 0; np < 4; np++)
                ldmx4(kb + np*4, sbase + KH_O + (uint32_t)((np*16 + b_row)*AP + t*32 + b_xtra));
#pragma unroll
            for (int mi = 0; mi < 2; mi++) {
                uint32_t ah[4];
                ldmx4(ah, sbase + QH_O + (uint32_t)((w*32 + mi*16 + a_row)*AP + t*32 + a_xtra));
#pragma unroll
                for (int ni = 0; ni < 8; ni++)
                    mma_f16(pacc[mi][ni], ah, &kb[(ni >> 1)*4 + (ni & 1)*2]);
            }
        }

        // causal mask + den partials
#pragma unroll
        for (int mi = 0; mi < 2; mi++)
#pragma unroll
            for (int ni = 0; ni < 8; ni++)
#pragma unroll
                for (int e = 0; e < 4; e++) {
                    int row = w*32 + mi*16 + (lane >> 2) + (e >> 1)*8;
                    int col = jb*64 + ni*8 + (lane & 3)*2 + (e & 1);
                    if (col > row) pacc[mi][ni][e] = 0.f;
                    else           den[mi][e >> 1] += pacc[mi][ni][e];
                }

        // GEMM2: num += P * Vstrip  (k = strip token dim, via Vt)
#pragma unroll
        for (int t = 0; t < 4; t++) {
            uint32_t vb[16];
#pragma unroll
            for (int np = 0; np < 4; np++)
                ldmx4(vb + np*4, sbase + VT_O + (uint32_t)((np*16 + b_row)*AP + t*32 + b_xtra));
#pragma unroll
            for (int mi = 0; mi < 2; mi++) {
                // acc->A-frag identity: tiles 2t & 2t+1 supply k16 tile t
                uint32_t ph[4];
                ph[0] = packh2(pacc[mi][2*t][0],   pacc[mi][2*t][1]);
                ph[1] = packh2(pacc[mi][2*t][2],   pacc[mi][2*t][3]);
                ph[2] = packh2(pacc[mi][2*t+1][0], pacc[mi][2*t+1][1]);
                ph[3] = packh2(pacc[mi][2*t+1][2], pacc[mi][2*t+1][3]);
#pragma unroll
                for (int ni = 0; ni < 8; ni++)
                    mma_f16(num[mi][ni], ph, &vb[(ni >> 1)*4 + (ni & 1)*2]);
            }
        }
    }

    // inter-chunk: num += Q * S (B = S^T)
#pragma unroll
    for (int t = 0; t < 4; t++) {
        uint32_t sb[16];
#pragma unroll
        for (int np = 0; np < 4; np++)
            ldmx4(sb + np*4, sbase + ST_O + (uint32_t)((np*16 + b_row)*AP + t*32 + b_xtra));
#pragma unroll
        for (int mi = 0; mi < 2; mi++) {
            uint32_t ah[4];
            ldmx4(ah, sbase + QH_O + (uint32_t)((w*32 + mi*16 + a_row)*AP + t*32 + a_xtra));
#pragma unroll
            for (int ni = 0; ni < 8; ni++)
                mma_f16(num[mi][ni], ah, &sb[(ni >> 1)*4 + (ni & 1)*2]);
        }
    }

    // den: quad reduce, then + q.Z
#pragma unroll
    for (int mi = 0; mi < 2; mi++)
#pragma unroll
        for (int hf = 0; hf < 2; hf++) {
            float d = den[mi][hf];
            d += __shfl_xor_sync(0xffffffffu, d, 1);
            d += __shfl_xor_sync(0xffffffffu, d, 2);
            int row = w*32 + mi*16 + (lane >> 2) + hf*8;
            float qz = 0.f;
            const char* qr = sm + QH_O + row*AP;
#pragma unroll
            for (int dd = 0; dd < 32; dd++) {
                float2 q2 = __half22float2(*(const __half2*)(qr + dd*4));
                float2 z2 = *(const float2*)(sm + Z_O + dd*8);
                qz += q2.x * z2.x + q2.y * z2.y;
            }
            den[mi][hf] = d + qz;
        }

    // divide + fp16 store to g_atth
    const size_t mbase = (size_t)(b * LL + c * CH);
#pragma unroll
    for (int mi = 0; mi < 2; mi++)
#pragma unroll
        for (int hf = 0; hf < 2; hf++) {
            int row = w*32 + mi*16 + (lane >> 2) + hf*8;
            float inv = 1.f / fmaxf(den[mi][hf], 1e-6f);
            size_t ob = (mbase + row) * EE + h * DH;
#pragma unroll
            for (int ni = 0; ni < 8; ni++) {
                int e = ni*8 + (lane & 3)*2;
                *(uint32_t*)(g_atth + ob + e) =
                    packh2(num[mi][ni][hf*2 + 0] * inv, num[mi][ni][hf*2 + 1] * inv);
            }
        }
}

// ---------------- launch ----------------
extern "C" void kernel_launch(void* const* d_in, const int* in_sizes, int n_in,
                              void* d_out, int out_size)
{
    const float* x    = (const float*)d_in[0];   // [B, L, E]
    const float* Wqkv = (const float*)d_in[1];   // [3E, E]
    const float* Wout = (const float*)d_in[2];   // [E, E]
    float* out = (float*)d_out;                  // [B, L, E]

    cudaFuncSetAttribute(attn_core_kernel,
                         cudaFuncAttributeMaxDynamicSharedMemorySize, ATTN_SMEM);
    const int gemm_smem = NSTAGE * GSTAGE;  // 165888
    cudaFuncSetAttribute(hmma_gemm_kernel<0>,
                         cudaFuncAttributeMaxDynamicSharedMemorySize, gemm_smem);
    cudaFuncSetAttribute(hmma_gemm_kernel<1>,
                         cudaFuncAttributeMaxDynamicSharedMemorySize, gemm_smem);

    // 0) fp16 conversion of inputs
    convert_kernel<0><<<(M1*EE/4 + 255)/256, 256>>>(x, M1*EE/4);
    convert_kernel<1><<<(NQKV*EE/4 + 255)/256, 256>>>(Wqkv, NQKV*EE/4);
    convert_kernel<2><<<(EE*EE/4 + 255)/256, 256>>>(Wout, EE*EE/4);

    // 1) QKV GEMM + feature-map -> fp16 q/k/v
    {
        dim3 grid(NQKV/128, M1/256);  // (24, 32)
        hmma_gemm_kernel<0><<<grid, 256, gemm_smem>>>(nullptr);
    }
    // 2) per-chunk Gram matrices
    {
        dim3 grid(NCH, HH, BB);
        chunk_kv_kernel<<<grid, 256>>>();
    }
    // 3) exclusive prefix (emits S^T fp16 + Z)
    prefix_kernel<<<BB*HH, 256>>>();
    // 4) attention core (fp16 HMMA, writes fp16 g_atth)
    {
        dim3 grid(NCH, HH, BB);
        attn_core_kernel<<<grid, 256, ATTN_SMEM>>>();
    }
    // 5) output GEMM: out = att @ Wout^T
    {
        dim3 grid(EE/128, M1/256);    // (8, 32)
        hmma_gemm_kernel<1><<<grid, 256, gemm_smem>>>(out);
    }
}

// round 11
// speedup vs baseline: 1.1285x; 1.1285x over previous
#include <cuda_runtime.h>
#include <cuda_fp16.h>
#include <math.h>
#include <stdint.h>

#define BB 2
#define LL 4096
#define EE 1024
#define HH 16
#define DH 64
#define CH 256
#define NCH 16
#define M1 (BB*LL)      // 8192
#define NQKV (3*EE)     // 3072

// ---------------- scratch (static device globals; no allocation) ----------------
__device__ __align__(16) __half g_xh[(size_t)M1*EE];
__device__ __align__(16) __half g_wqkvh[(size_t)NQKV*EE];
__device__ __align__(16) __half g_wouth[(size_t)EE*EE];
__device__ __align__(16) __half g_atth[(size_t)M1*EE];

__device__ __align__(16) __half g_qh[(size_t)BB*HH*LL*DH];
__device__ __align__(16) __half g_kh[(size_t)BB*HH*LL*DH];
__device__ __align__(16) __half g_vh[(size_t)BB*HH*LL*DH];

__device__ float g_G[(size_t)BB*HH*NCH*DH*DH];
__device__ __align__(16) __half g_STh[(size_t)BB*HH*NCH*DH*DH];
__device__ float g_zc[(size_t)BB*HH*NCH*DH];
__device__ float g_Z[(size_t)BB*HH*NCH*DH];

// ---------------- helpers ----------------
__device__ __forceinline__ uint32_t smem_u32(const void* p) {
    uint32_t a;
    asm("{ .reg .u64 t; cvta.to.shared.u64 t, %1; cvt.u32.u64 %0, t; }" : "=r"(a) : "l"(p));
    return a;
}
__device__ __forceinline__ void ldmx4(uint32_t* r, uint32_t a) {
    asm volatile("ldmatrix.sync.aligned.m8n8.x4.shared.b16 {%0,%1,%2,%3}, [%4];"
        : "=r"(r[0]), "=r"(r[1]), "=r"(r[2]), "=r"(r[3]) : "r"(a));
}
__device__ __forceinline__ void mma_f16(float* d, const uint32_t* a, const uint32_t* b) {
    asm volatile(
        "mma.sync.aligned.m16n8k16.row.col.f32.f16.f16.f32 "
        "{%0,%1,%2,%3}, {%4,%5,%6,%7}, {%8,%9}, {%0,%1,%2,%3};"
        : "+f"(d[0]), "+f"(d[1]), "+f"(d[2]), "+f"(d[3])
        : "r"(a[0]), "r"(a[1]), "r"(a[2]), "r"(a[3]), "r"(b[0]), "r"(b[1]));
}
__device__ __forceinline__ uint32_t packh2(float a, float b) {
    __half2 t = __halves2half2(__float2half_rn(a), __float2half_rn(b));
    return *(uint32_t*)&t;
}

#define CP_ASYNC16(s, g) \
    asm volatile("cp.async.cg.shared.global [%0], [%1], 16;" :: "r"(s), "l"(g))
#define CP_COMMIT() asm volatile("cp.async.commit_group;")
#define CP_WAIT0()  asm volatile("cp.async.wait_group 0;")

// ---------------- fp32 -> fp16 converter ----------------
template<int W>
__global__ __launch_bounds__(256)
void convert_kernel(const float* __restrict__ src, int n4)
{
    __half* dst = (W == 0) ? g_xh : (W == 1) ? g_wqkvh : g_wouth;
    int i = blockIdx.x * 256 + threadIdx.x;
    if (i >= n4) return;
    float4 v = ((const float4*)src)[i];
    ((__half2*)dst)[i*2 + 0] = __halves2half2(__float2half_rn(v.x), __float2half_rn(v.y));
    ((__half2*)dst)[i*2 + 1] = __halves2half2(__float2half_rn(v.z), __float2half_rn(v.w));
}

// ---------------- fp16 HMMA GEMM, double-buffered cp.async, BK=64 ----------------
// C[M,N] = A[M,K] * B[N,K]^T, fp32 accumulate.
// Block 128x128, 4 warps (2m x 2n), warp tile 64x64, 128 threads, 3 CTAs/SM.
// MODE 0: A=g_xh, B=g_wqkvh (N=3072), epilogue feature map -> fp16 q/k/v
// MODE 1: A=g_atth, B=g_wouth (N=1024), plain fp32 store to C
#define GP 144
#define GTILE (128*GP)       // 18432
#define GSTAGE (2*GTILE)     // 36864 (A + B)
#define GSMEM (2*GSTAGE)     // 73728
#define KC_N 16              // 1024 / 64

template<int MODE>
__global__ __launch_bounds__(128, 3)
void hmma_gemm_kernel(float* __restrict__ C)
{
    const __half* __restrict__ A = (MODE == 0) ? g_xh : g_atth;
    const __half* __restrict__ B = (MODE == 0) ? g_wqkvh : g_wouth;

    const int m0 = blockIdx.y * 128;
    const int n0 = blockIdx.x * 128;
    const int tid = threadIdx.x;
    const int wid = tid >> 5;
    const int lane = tid & 31;
    const int wm = (wid >> 1) * 64;   // 0, 64
    const int wn = (wid & 1) * 64;    // 0, 64

    extern __shared__ char smc[];
    const uint32_t base = smem_u32(smc);

    float acc[4][8][4];
#pragma unroll
    for (int a = 0; a < 4; a++)
#pragma unroll
        for (int b = 0; b < 8; b++)
#pragma unroll
            for (int c = 0; c < 4; c++) acc[a][b][c] = 0.f;

    const int g = lane >> 3, lr = lane & 7;
    const int a_row  = ((g & 1) << 3) + lr;
    const int a_xtra = (g & 2) ? 16 : 0;
    const int b_row  = ((g >> 1) << 3) + lr;
    const int b_xtra = (g & 1) ? 16 : 0;

    // cp.async slot decomposition: 128 threads, 16 rows x 8 c16-chunks per pass
    const int pf_row = tid >> 3;      // 0..15
    const int pf_c16 = tid & 7;

    auto prefetch = [&](int kc, int stg) {
        const int kb = kc * 64;
        const uint32_t sb = base + stg * GSTAGE;
#pragma unroll
        for (int i = 0; i < 8; i++) {
            int row = pf_row + i * 16;
            uint32_t so = (uint32_t)(row * GP + pf_c16 * 16);
            CP_ASYNC16(sb + so,         __cvta_generic_to_global(A + (size_t)(m0 + row) * EE + kb + pf_c16 * 8));
            CP_ASYNC16(sb + GTILE + so, __cvta_generic_to_global(B + (size_t)(n0 + row) * EE + kb + pf_c16 * 8));
        }
    };

    prefetch(0, 0); CP_COMMIT();

    int stg = 0;
    for (int kc = 0; kc < KC_N; kc++) {
        CP_WAIT0();
        __syncthreads();   // data for kc visible; buffer stg^1 free (all warps past kc-1)
        if (kc + 1 < KC_N) { prefetch(kc + 1, stg ^ 1); CP_COMMIT(); }

        const uint32_t sb = base + stg * GSTAGE;
#pragma unroll
        for (int t = 0; t < 4; t++) {
            uint32_t af[16];
#pragma unroll
            for (int mi = 0; mi < 4; mi++)
                ldmx4(af + mi*4, sb + (uint32_t)((wm + mi*16 + a_row) * GP + t*32 + a_xtra));
#pragma unroll
            for (int np = 0; np < 4; np++) {
                uint32_t bf[4];
                ldmx4(bf, sb + GTILE + (uint32_t)((wn + np*16 + b_row) * GP + t*32 + b_xtra));
#pragma unroll
                for (int mi = 0; mi < 4; mi++) {
                    mma_f16(acc[mi][2*np + 0], af + mi*4, bf + 0);
                    mma_f16(acc[mi][2*np + 1], af + mi*4, bf + 2);
                }
            }
        }
        stg ^= 1;
    }

    // epilogue
#pragma unroll
    for (int mi = 0; mi < 4; mi++) {
        int mrow = m0 + wm + mi*16 + (lane >> 2);
#pragma unroll
        for (int half = 0; half < 2; half++) {
            int m = mrow + half * 8;
#pragma unroll
            for (int ni = 0; ni < 8; ni++) {
                int n = n0 + wn + ni*8 + (lane & 3)*2;
                float v0 = acc[mi][ni][half*2 + 0];
                float v1 = acc[mi][ni][half*2 + 1];
                if (MODE == 1) {
                    *(float2*)(C + (size_t)m * EE + n) = make_float2(v0, v1);
                } else {
                    int s = n >> 10, h = (n >> 6) & 15, d = n & 63;
                    int bidx = m >> 12, l = m & 4095;
                    float r0, r1;
                    if (s == 0) {
                        r0 = (v0 > 0.f ? v0 + 1.f : expf(v0)) * 0.125f;
                        r1 = (v1 > 0.f ? v1 + 1.f : expf(v1)) * 0.125f;
                    } else if (s == 1) {
                        r0 = (v0 > 0.f ? v0 + 1.f : expf(v0));
                        r1 = (v1 > 0.f ? v1 + 1.f : expf(v1));
                    } else {
                        r0 = v0; r1 = v1;
                    }
                    __half* dst = (s == 0) ? g_qh : (s == 1) ? g_kh : g_vh;
                    size_t off = ((size_t)(bidx*HH + h) * LL + l) * DH + d;
                    *(uint32_t*)(dst + off) = packh2(r0, r1);
                }
            }
        }
    }
}

// ---------------- per-chunk Gram: G = K_c^T V_c  (64x64), z = sum K_c ----------------
__global__ __launch_bounds__(256)
void chunk_kv_kernel()
{
    const int c = blockIdx.x, h = blockIdx.y, b = blockIdx.z;
    const int bh = b * HH + h;
    const size_t tokbase = ((size_t)bh * LL + c * CH) * DH;
    const __half* kh = g_kh + tokbase;
    const __half* vh = g_vh + tokbase;

    __shared__ float ks[64][65];
    __shared__ float vs[64][65];

    const int tid = threadIdx.x;
    const int tx = tid & 15, ty = tid >> 4;

    float acc[4][4];
#pragma unroll
    for (int i = 0; i < 4; i++)
#pragma unroll
        for (int j = 0; j < 4; j++) acc[i][j] = 0.f;
    float zacc = 0.f;

    for (int lt = 0; lt < 4; lt++) {
#pragma unroll
        for (int t = 0; t < 4; t++) {
            int idx = tid + t * 256;
            int row = idx >> 4, c4 = idx & 15;
            size_t off = (size_t)(lt*64 + row) * DH + c4 * 4;
            float2 a0 = __half22float2(*(const __half2*)(kh + off));
            float2 a1 = __half22float2(*(const __half2*)(kh + off + 2));
            ks[row][c4*4+0] = a0.x; ks[row][c4*4+1] = a0.y;
            ks[row][c4*4+2] = a1.x; ks[row][c4*4+3] = a1.y;
            float2 b0 = __half22float2(*(const __half2*)(vh + off));
            float2 b1 = __half22float2(*(const __half2*)(vh + off + 2));
            vs[row][c4*4+0] = b0.x; vs[row][c4*4+1] = b0.y;
            vs[row][c4*4+2] = b1.x; vs[row][c4*4+3] = b1.y;
        }
        __syncthreads();
#pragma unroll 8
        for (int l = 0; l < 64; l++) {
            float a[4], bb[4];
#pragma unroll
            for (int i = 0; i < 4; i++) a[i] = ks[l][ty*4 + i];
#pragma unroll
            for (int j = 0; j < 4; j++) bb[j] = vs[l][tx*4 + j];
#pragma unroll
            for (int i = 0; i < 4; i++)
#pragma unroll
                for (int j = 0; j < 4; j++) acc[i][j] += a[i] * bb[j];
        }
        if (tid < 64) {
#pragma unroll 8
            for (int l = 0; l < 64; l++) zacc += ks[l][tid];
        }
        __syncthreads();
    }

    float* Gout = g_G + ((size_t)bh * NCH + c) * DH * DH;
#pragma unroll
    for (int i = 0; i < 4; i++)
#pragma unroll
        for (int j = 0; j < 4; j++)
            Gout[(ty*4 + i) * DH + tx*4 + j] = acc[i][j];
    if (tid < 64) g_zc[((size_t)bh * NCH + c) * DH + tid] = zacc;
}

// ---------------- exclusive prefix over chunks; emits S^T as fp16 ----------------
__global__ __launch_bounds__(256)
void prefix_kernel()
{
    const int bh = blockIdx.x;
    const int tid = threadIdx.x;
    for (int idx = tid; idx < DH*DH; idx += 256) {
        int d = idx >> 6, e = idx & 63;
        float run = 0.f;
        for (int c = 0; c < NCH; c++) {
            size_t gbase = ((size_t)bh * NCH + c) * DH * DH;
            g_STh[gbase + e*DH + d] = __float2half_rn(run);
            run += g_G[gbase + idx];
        }
    }
    if (tid < DH) {
        float run = 0.f;
        for (int c = 0; c < NCH; c++) {
            size_t o = ((size_t)bh * NCH + c) * DH + tid;
            g_Z[o] = run;
            run += g_zc[o];
        }
    }
}

// ---------------- attention core (fp16 HMMA): per (b,h,c), 256x64 tile ----------------
#define AP 144
#define QH_O  0
#define KH_O  36864
#define VT_O  46080
#define ST_O  55296
#define Z_O   64512
#define ATTN_SMEM (Z_O + 256)

__global__ __launch_bounds__(256, 1)
void attn_core_kernel()
{
    const int c = blockIdx.x, h = blockIdx.y, b = blockIdx.z;
    const int bh = b * HH + h;
    const size_t tokbase = (size_t)bh * LL + c * CH;

    extern __shared__ char sm[];
    const uint32_t sbase = smem_u32(sm);

    const int tid = threadIdx.x;
    const int w = tid >> 5;
    const int lane = tid & 31;
    const int g = lane >> 3, lr = lane & 7;
    const int a_row  = ((g & 1) << 3) + lr;
    const int a_xtra = (g & 2) ? 16 : 0;
    const int b_row  = ((g >> 1) << 3) + lr;
    const int b_xtra = (g & 1) ? 16 : 0;

    // load Q (256x64)
    {
        const __half* qh = g_qh + tokbase * DH;
#pragma unroll
        for (int t = 0; t < 8; t++) {
            int idx = tid + t * 256;
            int row = idx >> 3, c16 = idx & 7;
            *(uint4*)(sm + QH_O + row*AP + c16*16) = *(const uint4*)(qh + (size_t)row*DH + c16*8);
        }
    }
    // load S^T (64x64) + Z
    {
        const size_t stb = ((size_t)bh * NCH + c) * DH * DH;
#pragma unroll
        for (int t = 0; t < 2; t++) {
            int idx = tid + t * 256;
            int row = idx >> 3, c16 = idx & 7;
            *(uint4*)(sm + ST_O + row*AP + c16*16) = *(const uint4*)(g_STh + stb + (size_t)row*DH + c16*8);
        }
        if (tid < DH) *(float*)(sm + Z_O + tid*4) = g_Z[((size_t)bh * NCH + c) * DH + tid];
    }

    float num[2][8][4];
#pragma unroll
    for (int mi = 0; mi < 2; mi++)
#pragma unroll
        for (int ni = 0; ni < 8; ni++)
#pragma unroll
            for (int e = 0; e < 4; e++) num[mi][ni][e] = 0.f;
    float den[2][2] = {{0.f, 0.f}, {0.f, 0.f}};

    for (int jb = 0; jb < 4; jb++) {
        __syncthreads();   // strip buffers free (also orders Q/ST loads on jb==0)
        // load K strip (64x64)
        {
            const __half* kh = g_kh + (tokbase + jb*64) * DH;
#pragma unroll
            for (int t = 0; t < 2; t++) {
                int idx = tid + t * 256;
                int row = idx >> 3, c16 = idx & 7;
                *(uint4*)(sm + KH_O + row*AP + c16*16) = *(const uint4*)(kh + (size_t)row*DH + c16*8);
            }
        }
        // load + transpose V strip: Vt[e][m]
        {
            const __half* vh = g_vh + (tokbase + jb*64) * DH;
#pragma unroll
            for (int t = 0; t < 4; t++) {
                int s = tid + t * 256;
                int m = s >> 4, e = (s & 15) * 4;
                __half2 h0 = *(const __half2*)(vh + (size_t)m*DH + e);
                __half2 h1 = *(const __half2*)(vh + (size_t)m*DH + e + 2);
                *(__half*)(sm + VT_O + (e+0)*AP + m*2) = __low2half(h0);
                *(__half*)(sm + VT_O + (e+1)*AP + m*2) = __high2half(h0);
                *(__half*)(sm + VT_O + (e+2)*AP + m*2) = __low2half(h1);
                *(__half*)(sm + VT_O + (e+3)*AP + m*2) = __high2half(h1);
            }
        }
        __syncthreads();

        // GEMM1: P = Q * Kstrip^T  (warp: 32x64, k=64)
        float pacc[2][8][4];
#pragma unroll
        for (int mi = 0; mi < 2; mi++)
#pragma unroll
            for (int ni = 0; ni < 8; ni++)
#pragma unroll
                for (int e = 0; e < 4; e++) pacc[mi][ni][e] = 0.f;

#pragma unroll
        for (int t = 0; t < 4; t++) {
            uint32_t kb[16];
#pragma unroll
            for (int np = 0; np < 4; np++)
                ldmx4(kb + np*4, sbase + KH_O + (uint32_t)((np*16 + b_row)*AP + t*32 + b_xtra));
#pragma unroll
            for (int mi = 0; mi < 2; mi++) {
                uint32_t ah[4];
                ldmx4(ah, sbase + QH_O + (uint32_t)((w*32 + mi*16 + a_row)*AP + t*32 + a_xtra));
#pragma unroll
                for (int ni = 0; ni < 8; ni++)
                    mma_f16(pacc[mi][ni], ah, &kb[(ni >> 1)*4 + (ni & 1)*2]);
            }
        }

        // causal mask + den partials
#pragma unroll
        for (int mi = 0; mi < 2; mi++)
#pragma unroll
            for (int ni = 0; ni < 8; ni++)
#pragma unroll
                for (int e = 0; e < 4; e++) {
                    int row = w*32 + mi*16 + (lane >> 2) + (e >> 1)*8;
                    int col = jb*64 + ni*8 + (lane & 3)*2 + (e & 1);
                    if (col > row) pacc[mi][ni][e] = 0.f;
                    else           den[mi][e >> 1] += pacc[mi][ni][e];
                }

        // GEMM2: num += P * Vstrip  (k = strip token dim, via Vt)
#pragma unroll
        for (int t = 0; t < 4; t++) {
            uint32_t vb[16];
#pragma unroll
            for (int np = 0; np < 4; np++)
                ldmx4(vb + np*4, sbase + VT_O + (uint32_t)((np*16 + b_row)*AP + t*32 + b_xtra));
#pragma unroll
            for (int mi = 0; mi < 2; mi++) {
                // acc->A-frag identity: tiles 2t & 2t+1 supply k16 tile t
                uint32_t ph[4];
                ph[0] = packh2(pacc[mi][2*t][0],   pacc[mi][2*t][1]);
                ph[1] = packh2(pacc[mi][2*t][2],   pacc[mi][2*t][3]);
                ph[2] = packh2(pacc[mi][2*t+1][0], pacc[mi][2*t+1][1]);
                ph[3] = packh2(pacc[mi][2*t+1][2], pacc[mi][2*t+1][3]);
#pragma unroll
                for (int ni = 0; ni < 8; ni++)
                    mma_f16(num[mi][ni], ph, &vb[(ni >> 1)*4 + (ni & 1)*2]);
            }
        }
    }

    // inter-chunk: num += Q * S (B = S^T)
#pragma unroll
    for (int t = 0; t < 4; t++) {
        uint32_t sb[16];
#pragma unroll
        for (int np = 0; np < 4; np++)
            ldmx4(sb + np*4, sbase + ST_O + (uint32_t)((np*16 + b_row)*AP + t*32 + b_xtra));
#pragma unroll
        for (int mi = 0; mi < 2; mi++) {
            uint32_t ah[4];
            ldmx4(ah, sbase + QH_O + (uint32_t)((w*32 + mi*16 + a_row)*AP + t*32 + a_xtra));
#pragma unroll
            for (int ni = 0; ni < 8; ni++)
                mma_f16(num[mi][ni], ah, &sb[(ni >> 1)*4 + (ni & 1)*2]);
        }
    }

    // den: quad reduce, then + q.Z
#pragma unroll
    for (int mi = 0; mi < 2; mi++)
#pragma unroll
        for (int hf = 0; hf < 2; hf++) {
            float d = den[mi][hf];
            d += __shfl_xor_sync(0xffffffffu, d, 1);
            d += __shfl_xor_sync(0xffffffffu, d, 2);
            int row = w*32 + mi*16 + (lane >> 2) + hf*8;
            float qz = 0.f;
            const char* qr = sm + QH_O + row*AP;
#pragma unroll
            for (int dd = 0; dd < 32; dd++) {
                float2 q2 = __half22float2(*(const __half2*)(qr + dd*4));
                float2 z2 = *(const float2*)(sm + Z_O + dd*8);
                qz += q2.x * z2.x + q2.y * z2.y;
            }
            den[mi][hf] = d + qz;
        }

    // divide + fp16 store to g_atth
    const size_t mbase = (size_t)(b * LL + c * CH);
#pragma unroll
    for (int mi = 0; mi < 2; mi++)
#pragma unroll
        for (int hf = 0; hf < 2; hf++) {
            int row = w*32 + mi*16 + (lane >> 2) + hf*8;
            float inv = 1.f / fmaxf(den[mi][hf], 1e-6f);
            size_t ob = (mbase + row) * EE + h * DH;
#pragma unroll
            for (int ni = 0; ni < 8; ni++) {
                int e = ni*8 + (lane & 3)*2;
                *(uint32_t*)(g_atth + ob + e) =
                    packh2(num[mi][ni][hf*2 + 0] * inv, num[mi][ni][hf*2 + 1] * inv);
            }
        }
}

// ---------------- launch ----------------
extern "C" void kernel_launch(void* const* d_in, const int* in_sizes, int n_in,
                              void* d_out, int out_size)
{
    const float* x    = (const float*)d_in[0];   // [B, L, E]
    const float* Wqkv = (const float*)d_in[1];   // [3E, E]
    const float* Wout = (const float*)d_in[2];   // [E, E]
    float* out = (float*)d_out;                  // [B, L, E]

    cudaFuncSetAttribute(attn_core_kernel,
                         cudaFuncAttributeMaxDynamicSharedMemorySize, ATTN_SMEM);
    cudaFuncSetAttribute(hmma_gemm_kernel<0>,
                         cudaFuncAttributeMaxDynamicSharedMemorySize, GSMEM);
    cudaFuncSetAttribute(hmma_gemm_kernel<1>,
                         cudaFuncAttributeMaxDynamicSharedMemorySize, GSMEM);

    // 0) fp16 conversion of inputs
    convert_kernel<0><<<(M1*EE/4 + 255)/256, 256>>>(x, M1*EE/4);
    convert_kernel<1><<<(NQKV*EE/4 + 255)/256, 256>>>(Wqkv, NQKV*EE/4);
    convert_kernel<2><<<(EE*EE/4 + 255)/256, 256>>>(Wout, EE*EE/4);

    // 1) QKV GEMM + feature-map -> fp16 q/k/v
    {
        dim3 grid(NQKV/128, M1/128);  // (24, 64)
        hmma_gemm_kernel<0><<<grid, 128, GSMEM>>>(nullptr);
    }
    // 2) per-chunk Gram matrices
    {
        dim3 grid(NCH, HH, BB);
        chunk_kv_kernel<<<grid, 256>>>();
    }
    // 3) exclusive prefix (emits S^T fp16 + Z)
    prefix_kernel<<<BB*HH, 256>>>();
    // 4) attention core (fp16 HMMA, writes fp16 g_atth)
    {
        dim3 grid(NCH, HH, BB);
        attn_core_kernel<<<grid, 256, ATTN_SMEM>>>();
    }
    // 5) output GEMM: out = att @ Wout^T
    {
        dim3 grid(EE/128, M1/128);    // (8, 64)
        hmma_gemm_kernel<1><<<grid, 128, GSMEM>>>(out);
    }
}

// round 12
// speedup vs baseline: 1.1685x; 1.0355x over previous
#include <cuda_runtime.h>
#include <cuda_fp16.h>
#include <math.h>
#include <stdint.h>

#define BB 2
#define LL 4096
#define EE 1024
#define HH 16
#define DH 64
#define CH 256
#define NCH 16
#define M1 (BB*LL)      // 8192
#define NQKV (3*EE)     // 3072

// ---------------- scratch (static device globals; no allocation) ----------------
__device__ __align__(16) __half g_xh[(size_t)M1*EE];
__device__ __align__(16) __half g_wqkvh[(size_t)NQKV*EE];
__device__ __align__(16) __half g_wouth[(size_t)EE*EE];
__device__ __align__(16) __half g_atth[(size_t)M1*EE];

__device__ __align__(16) __half g_qh[(size_t)BB*HH*LL*DH];
__device__ __align__(16) __half g_kh[(size_t)BB*HH*LL*DH];
__device__ __align__(16) __half g_vh[(size_t)BB*HH*LL*DH];

__device__ float g_G[(size_t)BB*HH*NCH*DH*DH];
__device__ __align__(16) __half g_STh[(size_t)BB*HH*NCH*DH*DH];
__device__ float g_zc[(size_t)BB*HH*NCH*DH];
__device__ float g_Z[(size_t)BB*HH*NCH*DH];

// ---------------- helpers ----------------
__device__ __forceinline__ uint32_t smem_u32(const void* p) {
    uint32_t a;
    asm("{ .reg .u64 t; cvta.to.shared.u64 t, %1; cvt.u32.u64 %0, t; }" : "=r"(a) : "l"(p));
    return a;
}
__device__ __forceinline__ void ldmx4(uint32_t* r, uint32_t a) {
    asm volatile("ldmatrix.sync.aligned.m8n8.x4.shared.b16 {%0,%1,%2,%3}, [%4];"
        : "=r"(r[0]), "=r"(r[1]), "=r"(r[2]), "=r"(r[3]) : "r"(a));
}
__device__ __forceinline__ void ldmx4t(uint32_t* r, uint32_t a) {
    asm volatile("ldmatrix.sync.aligned.m8n8.x4.trans.shared.b16 {%0,%1,%2,%3}, [%4];"
        : "=r"(r[0]), "=r"(r[1]), "=r"(r[2]), "=r"(r[3]) : "r"(a));
}
__device__ __forceinline__ void mma_f16(float* d, const uint32_t* a, const uint32_t* b) {
    asm volatile(
        "mma.sync.aligned.m16n8k16.row.col.f32.f16.f16.f32 "
        "{%0,%1,%2,%3}, {%4,%5,%6,%7}, {%8,%9}, {%0,%1,%2,%3};"
        : "+f"(d[0]), "+f"(d[1]), "+f"(d[2]), "+f"(d[3])
        : "r"(a[0]), "r"(a[1]), "r"(a[2]), "r"(a[3]), "r"(b[0]), "r"(b[1]));
}
__device__ __forceinline__ uint32_t packh2(float a, float b) {
    __half2 t = __halves2half2(__float2half_rn(a), __float2half_rn(b));
    return *(uint32_t*)&t;
}

#define CP_ASYNC16(s, g) \
    asm volatile("cp.async.cg.shared.global [%0], [%1], 16;" :: "r"(s), "l"(g))
#define CP_COMMIT() asm volatile("cp.async.commit_group;")
#define CP_WAIT0()  asm volatile("cp.async.wait_group 0;")

// ---------------- fp32 -> fp16 converter ----------------
template<int W>
__global__ __launch_bounds__(256)
void convert_kernel(const float* __restrict__ src, int n4)
{
    __half* dst = (W == 0) ? g_xh : (W == 1) ? g_wqkvh : g_wouth;
    int i = blockIdx.x * 256 + threadIdx.x;
    if (i >= n4) return;
    float4 v = ((const float4*)src)[i];
    ((__half2*)dst)[i*2 + 0] = __halves2half2(__float2half_rn(v.x), __float2half_rn(v.y));
    ((__half2*)dst)[i*2 + 1] = __halves2half2(__float2half_rn(v.z), __float2half_rn(v.w));
}

// ---------------- fp16 HMMA GEMM (unchanged from R11 — best known) ----------------
#define GP 144
#define GTILE (128*GP)       // 18432
#define GSTAGE (2*GTILE)     // 36864 (A + B)
#define GSMEM (2*GSTAGE)     // 73728
#define KC_N 16              // 1024 / 64

template<int MODE>
__global__ __launch_bounds__(128, 3)
void hmma_gemm_kernel(float* __restrict__ C)
{
    const __half* __restrict__ A = (MODE == 0) ? g_xh : g_atth;
    const __half* __restrict__ B = (MODE == 0) ? g_wqkvh : g_wouth;

    const int m0 = blockIdx.y * 128;
    const int n0 = blockIdx.x * 128;
    const int tid = threadIdx.x;
    const int wid = tid >> 5;
    const int lane = tid & 31;
    const int wm = (wid >> 1) * 64;
    const int wn = (wid & 1) * 64;

    extern __shared__ char smc[];
    const uint32_t base = smem_u32(smc);

    float acc[4][8][4];
#pragma unroll
    for (int a = 0; a < 4; a++)
#pragma unroll
        for (int b = 0; b < 8; b++)
#pragma unroll
            for (int c = 0; c < 4; c++) acc[a][b][c] = 0.f;

    const int g = lane >> 3, lr = lane & 7;
    const int a_row  = ((g & 1) << 3) + lr;
    const int a_xtra = (g & 2) ? 16 : 0;
    const int b_row  = ((g >> 1) << 3) + lr;
    const int b_xtra = (g & 1) ? 16 : 0;

    const int pf_row = tid >> 3;
    const int pf_c16 = tid & 7;

    auto prefetch = [&](int kc, int stg) {
        const int kb = kc * 64;
        const uint32_t sb = base + stg * GSTAGE;
#pragma unroll
        for (int i = 0; i < 8; i++) {
            int row = pf_row + i * 16;
            uint32_t so = (uint32_t)(row * GP + pf_c16 * 16);
            CP_ASYNC16(sb + so,         __cvta_generic_to_global(A + (size_t)(m0 + row) * EE + kb + pf_c16 * 8));
            CP_ASYNC16(sb + GTILE + so, __cvta_generic_to_global(B + (size_t)(n0 + row) * EE + kb + pf_c16 * 8));
        }
    };

    prefetch(0, 0); CP_COMMIT();

    int stg = 0;
    for (int kc = 0; kc < KC_N; kc++) {
        CP_WAIT0();
        __syncthreads();
        if (kc + 1 < KC_N) { prefetch(kc + 1, stg ^ 1); CP_COMMIT(); }

        const uint32_t sb = base + stg * GSTAGE;
#pragma unroll
        for (int t = 0; t < 4; t++) {
            uint32_t af[16];
#pragma unroll
            for (int mi = 0; mi < 4; mi++)
                ldmx4(af + mi*4, sb + (uint32_t)((wm + mi*16 + a_row) * GP + t*32 + a_xtra));
#pragma unroll
            for (int np = 0; np < 4; np++) {
                uint32_t bf[4];
                ldmx4(bf, sb + GTILE + (uint32_t)((wn + np*16 + b_row) * GP + t*32 + b_xtra));
#pragma unroll
                for (int mi = 0; mi < 4; mi++) {
                    mma_f16(acc[mi][2*np + 0], af + mi*4, bf + 0);
                    mma_f16(acc[mi][2*np + 1], af + mi*4, bf + 2);
                }
            }
        }
        stg ^= 1;
    }

    // epilogue
#pragma unroll
    for (int mi = 0; mi < 4; mi++) {
        int mrow = m0 + wm + mi*16 + (lane >> 2);
#pragma unroll
        for (int half = 0; half < 2; half++) {
            int m = mrow + half * 8;
#pragma unroll
            for (int ni = 0; ni < 8; ni++) {
                int n = n0 + wn + ni*8 + (lane & 3)*2;
                float v0 = acc[mi][ni][half*2 + 0];
                float v1 = acc[mi][ni][half*2 + 1];
                if (MODE == 1) {
                    *(float2*)(C + (size_t)m * EE + n) = make_float2(v0, v1);
                } else {
                    int s = n >> 10, h = (n >> 6) & 15, d = n & 63;
                    int bidx = m >> 12, l = m & 4095;
                    float r0, r1;
                    if (s == 0) {
                        r0 = (v0 > 0.f ? v0 + 1.f : expf(v0)) * 0.125f;
                        r1 = (v1 > 0.f ? v1 + 1.f : expf(v1)) * 0.125f;
                    } else if (s == 1) {
                        r0 = (v0 > 0.f ? v0 + 1.f : expf(v0));
                        r1 = (v1 > 0.f ? v1 + 1.f : expf(v1));
                    } else {
                        r0 = v0; r1 = v1;
                    }
                    __half* dst = (s == 0) ? g_qh : (s == 1) ? g_kh : g_vh;
                    size_t off = ((size_t)(bidx*HH + h) * LL + l) * DH + d;
                    *(uint32_t*)(dst + off) = packh2(r0, r1);
                }
            }
        }
    }
}

// ---------------- per-chunk Gram: G = K_c^T V_c  (64x64), z = sum K_c ----------------
__global__ __launch_bounds__(256)
void chunk_kv_kernel()
{
    const int c = blockIdx.x, h = blockIdx.y, b = blockIdx.z;
    const int bh = b * HH + h;
    const size_t tokbase = ((size_t)bh * LL + c * CH) * DH;
    const __half* kh = g_kh + tokbase;
    const __half* vh = g_vh + tokbase;

    __shared__ float ks[64][65];
    __shared__ float vs[64][65];

    const int tid = threadIdx.x;
    const int tx = tid & 15, ty = tid >> 4;

    float acc[4][4];
#pragma unroll
    for (int i = 0; i < 4; i++)
#pragma unroll
        for (int j = 0; j < 4; j++) acc[i][j] = 0.f;
    float zacc = 0.f;

    for (int lt = 0; lt < 4; lt++) {
#pragma unroll
        for (int t = 0; t < 4; t++) {
            int idx = tid + t * 256;
            int row = idx >> 4, c4 = idx & 15;
            size_t off = (size_t)(lt*64 + row) * DH + c4 * 4;
            float2 a0 = __half22float2(*(const __half2*)(kh + off));
            float2 a1 = __half22float2(*(const __half2*)(kh + off + 2));
            ks[row][c4*4+0] = a0.x; ks[row][c4*4+1] = a0.y;
            ks[row][c4*4+2] = a1.x; ks[row][c4*4+3] = a1.y;
            float2 b0 = __half22float2(*(const __half2*)(vh + off));
            float2 b1 = __half22float2(*(const __half2*)(vh + off + 2));
            vs[row][c4*4+0] = b0.x; vs[row][c4*4+1] = b0.y;
            vs[row][c4*4+2] = b1.x; vs[row][c4*4+3] = b1.y;
        }
        __syncthreads();
#pragma unroll 8
        for (int l = 0; l < 64; l++) {
            float a[4], bb[4];
#pragma unroll
            for (int i = 0; i < 4; i++) a[i] = ks[l][ty*4 + i];
#pragma unroll
            for (int j = 0; j < 4; j++) bb[j] = vs[l][tx*4 + j];
#pragma unroll
            for (int i = 0; i < 4; i++)
#pragma unroll
                for (int j = 0; j < 4; j++) acc[i][j] += a[i] * bb[j];
        }
        if (tid < 64) {
#pragma unroll 8
            for (int l = 0; l < 64; l++) zacc += ks[l][tid];
        }
        __syncthreads();
    }

    float* Gout = g_G + ((size_t)bh * NCH + c) * DH * DH;
#pragma unroll
    for (int i = 0; i < 4; i++)
#pragma unroll
        for (int j = 0; j < 4; j++)
            Gout[(ty*4 + i) * DH + tx*4 + j] = acc[i][j];
    if (tid < 64) g_zc[((size_t)bh * NCH + c) * DH + tid] = zacc;
}

// ---------------- exclusive prefix over chunks; emits S^T as fp16 ----------------
__global__ __launch_bounds__(256)
void prefix_kernel()
{
    const int bh = blockIdx.x;
    const int tid = threadIdx.x;
    for (int idx = tid; idx < DH*DH; idx += 256) {
        int d = idx >> 6, e = idx & 63;
        float run = 0.f;
        for (int c = 0; c < NCH; c++) {
            size_t gbase = ((size_t)bh * NCH + c) * DH * DH;
            g_STh[gbase + e*DH + d] = __float2half_rn(run);
            run += g_G[gbase + idx];
        }
    }
    if (tid < DH) {
        float run = 0.f;
        for (int c = 0; c < NCH; c++) {
            size_t o = ((size_t)bh * NCH + c) * DH + tid;
            g_Z[o] = run;
            run += g_zc[o];
        }
    }
}

// ---------------- attention core (fp16 HMMA): per (b,h,c,rh), 128x64 tile ----------------
// 128 threads, 3 CTAs/SM. Causal strip-skip: row-half rh only needs jb < 2*rh+2.
// V loaded raw; B-fragments for P*V via ldmatrix.x4.trans (no transpose staging).
#define AP 144
#define QH_O  0
#define KH_O  18432
#define VH_O  27648
#define ST_O  36864
#define Z_O   46080
#define ATTN_SMEM (Z_O + 256)

__global__ __launch_bounds__(128, 3)
void attn_core_kernel()
{
    const int cc = blockIdx.x;
    const int c = cc >> 1, rh = cc & 1;
    const int h = blockIdx.y, b = blockIdx.z;
    const int bh = b * HH + h;
    const size_t tokbase = (size_t)bh * LL + c * CH;
    const int rowbase = rh * 128;

    extern __shared__ char sm[];
    const uint32_t sbase = smem_u32(sm);

    const int tid = threadIdx.x;
    const int w = tid >> 5;
    const int lane = tid & 31;
    const int g = lane >> 3, lr = lane & 7;
    const int a_row  = ((g & 1) << 3) + lr;
    const int a_xtra = (g & 2) ? 16 : 0;
    const int b_row  = ((g >> 1) << 3) + lr;
    const int b_xtra = (g & 1) ? 16 : 0;
    // trans-V per-lane address parts: row = t*16 + (lane&15); col bytes = np*32 + ((lane>>4)<<4)
    const int vt_row = lane & 15;
    const int vt_cb  = (lane >> 4) << 4;

    // load Q (128 rows x 64)
    {
        const __half* qh = g_qh + (tokbase + rowbase) * DH;
#pragma unroll
        for (int t = 0; t < 8; t++) {
            int idx = tid + t * 128;
            int row = idx >> 3, c16 = idx & 7;
            *(uint4*)(sm + QH_O + row*AP + c16*16) = *(const uint4*)(qh + (size_t)row*DH + c16*8);
        }
    }
    // load S^T (64x64) + Z
    {
        const size_t stb = ((size_t)bh * NCH + c) * DH * DH;
#pragma unroll
        for (int t = 0; t < 4; t++) {
            int idx = tid + t * 128;
            int row = idx >> 3, c16 = idx & 7;
            *(uint4*)(sm + ST_O + row*AP + c16*16) = *(const uint4*)(g_STh + stb + (size_t)row*DH + c16*8);
        }
        if (tid < DH) *(float*)(sm + Z_O + tid*4) = g_Z[((size_t)bh * NCH + c) * DH + tid];
    }

    float num[2][8][4];
#pragma unroll
    for (int mi = 0; mi < 2; mi++)
#pragma unroll
        for (int ni = 0; ni < 8; ni++)
#pragma unroll
            for (int e = 0; e < 4; e++) num[mi][ni][e] = 0.f;
    float den[2][2] = {{0.f, 0.f}, {0.f, 0.f}};

    const int jb_max = rh * 2 + 2;   // causal: strips beyond diagonal contribute 0
    for (int jb = 0; jb < jb_max; jb++) {
        __syncthreads();
        // load K strip (64x64) and V strip (64x64), both row-major
        {
            const __half* kh = g_kh + (tokbase + jb*64) * DH;
            const __half* vh = g_vh + (tokbase + jb*64) * DH;
#pragma unroll
            for (int t = 0; t < 4; t++) {
                int idx = tid + t * 128;
                int row = idx >> 3, c16 = idx & 7;
                *(uint4*)(sm + KH_O + row*AP + c16*16) = *(const uint4*)(kh + (size_t)row*DH + c16*8);
                *(uint4*)(sm + VH_O + row*AP + c16*16) = *(const uint4*)(vh + (size_t)row*DH + c16*8);
            }
        }
        __syncthreads();

        // GEMM1: P = Q_half * Kstrip^T  (warp: 32x64, k=64)
        float pacc[2][8][4];
#pragma unroll
        for (int mi = 0; mi < 2; mi++)
#pragma unroll
            for (int ni = 0; ni < 8; ni++)
#pragma unroll
                for (int e = 0; e < 4; e++) pacc[mi][ni][e] = 0.f;

#pragma unroll
        for (int t = 0; t < 4; t++) {
            uint32_t kb[16];
#pragma unroll
            for (int np = 0; np < 4; np++)
                ldmx4(kb + np*4, sbase + KH_O + (uint32_t)((np*16 + b_row)*AP + t*32 + b_xtra));
#pragma unroll
            for (int mi = 0; mi < 2; mi++) {
                uint32_t ah[4];
                ldmx4(ah, sbase + QH_O + (uint32_t)((w*32 + mi*16 + a_row)*AP + t*32 + a_xtra));
#pragma unroll
                for (int ni = 0; ni < 8; ni++)
                    mma_f16(pacc[mi][ni], ah, &kb[(ni >> 1)*4 + (ni & 1)*2]);
            }
        }

        // causal mask + den partials (only the diagonal strip actually masks)
        const bool diag = (jb*64 == rowbase + 64*0) || true;  // keep mask generic
#pragma unroll
        for (int mi = 0; mi < 2; mi++)
#pragma unroll
            for (int ni = 0; ni < 8; ni++)
#pragma unroll
                for (int e = 0; e < 4; e++) {
                    int row = rowbase + w*32 + mi*16 + (lane >> 2) + (e >> 1)*8;
                    int col = jb*64 + ni*8 + (lane & 3)*2 + (e & 1);
                    if (col > row) pacc[mi][ni][e] = 0.f;
                    else           den[mi][e >> 1] += pacc[mi][ni][e];
                }
        (void)diag;

        // GEMM2: num += P * Vstrip  (B-fragments via ldmatrix.trans on row-major V)
#pragma unroll
        for (int t = 0; t < 4; t++) {
            uint32_t vb[16];
#pragma unroll
            for (int np = 0; np < 4; np++)
                ldmx4t(vb + np*4, sbase + VH_O +
                       (uint32_t)((t*16 + vt_row)*AP + np*32 + vt_cb));
#pragma unroll
            for (int mi = 0; mi < 2; mi++) {
                // acc->A-frag identity: tiles 2t & 2t+1 supply k16 tile t
                uint32_t ph[4];
                ph[0] = packh2(pacc[mi][2*t][0],   pacc[mi][2*t][1]);
                ph[1] = packh2(pacc[mi][2*t][2],   pacc[mi][2*t][3]);
                ph[2] = packh2(pacc[mi][2*t+1][0], pacc[mi][2*t+1][1]);
                ph[3] = packh2(pacc[mi][2*t+1][2], pacc[mi][2*t+1][3]);
#pragma unroll
                for (int ni = 0; ni < 8; ni++)
                    mma_f16(num[mi][ni], ph, &vb[(ni >> 1)*4 + (ni & 1)*2]);
            }
        }
    }

    // inter-chunk: num += Q * S (B = S^T)
#pragma unroll
    for (int t = 0; t < 4; t++) {
        uint32_t sb[16];
#pragma unroll
        for (int np = 0; np < 4; np++)
            ldmx4(sb + np*4, sbase + ST_O + (uint32_t)((np*16 + b_row)*AP + t*32 + b_xtra));
#pragma unroll
        for (int mi = 0; mi < 2; mi++) {
            uint32_t ah[4];
            ldmx4(ah, sbase + QH_O + (uint32_t)((w*32 + mi*16 + a_row)*AP + t*32 + a_xtra));
#pragma unroll
            for (int ni = 0; ni < 8; ni++)
                mma_f16(num[mi][ni], ah, &sb[(ni >> 1)*4 + (ni & 1)*2]);
        }
    }

    // den: quad reduce, then + q.Z
#pragma unroll
    for (int mi = 0; mi < 2; mi++)
#pragma unroll
        for (int hf = 0; hf < 2; hf++) {
            float d = den[mi][hf];
            d += __shfl_xor_sync(0xffffffffu, d, 1);
            d += __shfl_xor_sync(0xffffffffu, d, 2);
            int row = w*32 + mi*16 + (lane >> 2) + hf*8;   // smem-local row
            float qz = 0.f;
            const char* qr = sm + QH_O + row*AP;
#pragma unroll
            for (int dd = 0; dd < 32; dd++) {
                float2 q2 = __half22float2(*(const __half2*)(qr + dd*4));
                float2 z2 = *(const float2*)(sm + Z_O + dd*8);
                qz += q2.x * z2.x + q2.y * z2.y;
            }
            den[mi][hf] = d + qz;
        }

    // divide + fp16 store to g_atth
    const size_t mbase = (size_t)(b * LL + c * CH) + rowbase;
#pragma unroll
    for (int mi = 0; mi < 2; mi++)
#pragma unroll
        for (int hf = 0; hf < 2; hf++) {
            int row = w*32 + mi*16 + (lane >> 2) + hf*8;
            float inv = 1.f / fmaxf(den[mi][hf], 1e-6f);
            size_t ob = (mbase + row) * EE + h * DH;
#pragma unroll
            for (int ni = 0; ni < 8; ni++) {
                int e = ni*8 + (lane & 3)*2;
                *(uint32_t*)(g_atth + ob + e) =
                    packh2(num[mi][ni][hf*2 + 0] * inv, num[mi][ni][hf*2 + 1] * inv);
            }
        }
}

// ---------------- launch ----------------
extern "C" void kernel_launch(void* const* d_in, const int* in_sizes, int n_in,
                              void* d_out, int out_size)
{
    const float* x    = (const float*)d_in[0];   // [B, L, E]
    const float* Wqkv = (const float*)d_in[1];   // [3E, E]
    const float* Wout = (const float*)d_in[2];   // [E, E]
    float* out = (float*)d_out;                  // [B, L, E]

    cudaFuncSetAttribute(attn_core_kernel,
                         cudaFuncAttributeMaxDynamicSharedMemorySize, ATTN_SMEM);
    cudaFuncSetAttribute(hmma_gemm_kernel<0>,
                         cudaFuncAttributeMaxDynamicSharedMemorySize, GSMEM);
    cudaFuncSetAttribute(hmma_gemm_kernel<1>,
                         cudaFuncAttributeMaxDynamicSharedMemorySize, GSMEM);

    // 0) fp16 conversion of inputs
    convert_kernel<0><<<(M1*EE/4 + 255)/256, 256>>>(x, M1*EE/4);
    convert_kernel<1><<<(NQKV*EE/4 + 255)/256, 256>>>(Wqkv, NQKV*EE/4);
    convert_kernel<2><<<(EE*EE/4 + 255)/256, 256>>>(Wout, EE*EE/4);

    // 1) QKV GEMM + feature-map -> fp16 q/k/v
    {
        dim3 grid(NQKV/128, M1/128);  // (24, 64)
        hmma_gemm_kernel<0><<<grid, 128, GSMEM>>>(nullptr);
    }
    // 2) per-chunk Gram matrices
    {
        dim3 grid(NCH, HH, BB);
        chunk_kv_kernel<<<grid, 256>>>();
    }
    // 3) exclusive prefix (emits S^T fp16 + Z)
    prefix_kernel<<<BB*HH, 256>>>();
    // 4) attention core (fp16 HMMA, 128-row half-tiles, causal strip-skip)
    {
        dim3 grid(NCH*2, HH, BB);
        attn_core_kernel<<<grid, 128, ATTN_SMEM>>>();
    }
    // 5) output GEMM: out = att @ Wout^T
    {
        dim3 grid(EE/128, M1/128);    // (8, 64)
        hmma_gemm_kernel<1><<<grid, 128, GSMEM>>>(out);
    }
}

// round 13
// speedup vs baseline: 1.2797x; 1.0952x over previous
#include <cuda_runtime.h>
#include <cuda_fp16.h>
#include <math.h>
#include <stdint.h>

#define BB 2
#define LL 4096
#define EE 1024
#define HH 16
#define DH 64
#define CH 256
#define NCH 16
#define M1 (BB*LL)      // 8192
#define NQKV (3*EE)     // 3072

// ---------------- scratch (static device globals; no allocation) ----------------
__device__ __align__(16) __half g_xh[(size_t)M1*EE];
__device__ __align__(16) __half g_wqkvh[(size_t)NQKV*EE];
__device__ __align__(16) __half g_wouth[(size_t)EE*EE];
__device__ __align__(16) __half g_atth[(size_t)M1*EE];

__device__ __align__(16) __half g_qh[(size_t)BB*HH*LL*DH];
__device__ __align__(16) __half g_kh[(size_t)BB*HH*LL*DH];
__device__ __align__(16) __half g_vh[(size_t)BB*HH*LL*DH];

__device__ float g_G[(size_t)BB*HH*NCH*DH*DH];
__device__ __align__(16) __half g_STh[(size_t)BB*HH*NCH*DH*DH];
__device__ float g_zc[(size_t)BB*HH*NCH*DH];
__device__ float g_Z[(size_t)BB*HH*NCH*DH];

// ---------------- helpers ----------------
__device__ __forceinline__ uint32_t smem_u32(const void* p) {
    uint32_t a;
    asm("{ .reg .u64 t; cvta.to.shared.u64 t, %1; cvt.u32.u64 %0, t; }" : "=r"(a) : "l"(p));
    return a;
}
__device__ __forceinline__ void ldmx4(uint32_t* r, uint32_t a) {
    asm volatile("ldmatrix.sync.aligned.m8n8.x4.shared.b16 {%0,%1,%2,%3}, [%4];"
        : "=r"(r[0]), "=r"(r[1]), "=r"(r[2]), "=r"(r[3]) : "r"(a));
}
__device__ __forceinline__ void ldmx4t(uint32_t* r, uint32_t a) {
    asm volatile("ldmatrix.sync.aligned.m8n8.x4.trans.shared.b16 {%0,%1,%2,%3}, [%4];"
        : "=r"(r[0]), "=r"(r[1]), "=r"(r[2]), "=r"(r[3]) : "r"(a));
}
__device__ __forceinline__ void mma_f16(float* d, const uint32_t* a, const uint32_t* b) {
    asm volatile(
        "mma.sync.aligned.m16n8k16.row.col.f32.f16.f16.f32 "
        "{%0,%1,%2,%3}, {%4,%5,%6,%7}, {%8,%9}, {%0,%1,%2,%3};"
        : "+f"(d[0]), "+f"(d[1]), "+f"(d[2]), "+f"(d[3])
        : "r"(a[0]), "r"(a[1]), "r"(a[2]), "r"(a[3]), "r"(b[0]), "r"(b[1]));
}
__device__ __forceinline__ uint32_t packh2(float a, float b) {
    __half2 t = __halves2half2(__float2half_rn(a), __float2half_rn(b));
    return *(uint32_t*)&t;
}

#define CP_ASYNC16(s, g) \
    asm volatile("cp.async.cg.shared.global [%0], [%1], 16;" :: "r"(s), "l"(g))
#define CP_COMMIT() asm volatile("cp.async.commit_group;")
#define CP_WAIT0()  asm volatile("cp.async.wait_group 0;")

// ---------------- fp32 -> fp16 converter (all three inputs, one launch) ----------------
#define N4_X    (M1*EE/4)      // 2097152
#define N4_WQKV (NQKV*EE/4)    // 786432
#define N4_WOUT (EE*EE/4)      // 262144
#define N4_TOT  (N4_X + N4_WQKV + N4_WOUT)

__global__ __launch_bounds__(256)
void convert_all_kernel(const float* __restrict__ x,
                        const float* __restrict__ wqkv,
                        const float* __restrict__ wout)
{
    int i = blockIdx.x * 256 + threadIdx.x;
    if (i >= N4_TOT) return;
    const float* src;
    __half* dst;
    int j = i;
    if (j < N4_X)                { src = x;    dst = g_xh; }
    else if ((j -= N4_X) < N4_WQKV) { src = wqkv; dst = g_wqkvh; }
    else { j -= N4_WQKV;           src = wout; dst = g_wouth; }
    float4 v = ((const float4*)src)[j];
    ((__half2*)dst)[j*2 + 0] = __halves2half2(__float2half_rn(v.x), __float2half_rn(v.y));
    ((__half2*)dst)[j*2 + 1] = __halves2half2(__float2half_rn(v.z), __float2half_rn(v.w));
}

// ---------------- fp16 HMMA GEMM (unchanged from R11 — best known) ----------------
#define GP 144
#define GTILE (128*GP)       // 18432
#define GSTAGE (2*GTILE)     // 36864 (A + B)
#define GSMEM (2*GSTAGE)     // 73728
#define KC_N 16              // 1024 / 64

template<int MODE>
__global__ __launch_bounds__(128, 3)
void hmma_gemm_kernel(float* __restrict__ C)
{
    const __half* __restrict__ A = (MODE == 0) ? g_xh : g_atth;
    const __half* __restrict__ B = (MODE == 0) ? g_wqkvh : g_wouth;

    const int m0 = blockIdx.y * 128;
    const int n0 = blockIdx.x * 128;
    const int tid = threadIdx.x;
    const int wid = tid >> 5;
    const int lane = tid & 31;
    const int wm = (wid >> 1) * 64;
    const int wn = (wid & 1) * 64;

    extern __shared__ char smc[];
    const uint32_t base = smem_u32(smc);

    float acc[4][8][4];
#pragma unroll
    for (int a = 0; a < 4; a++)
#pragma unroll
        for (int b = 0; b < 8; b++)
#pragma unroll
            for (int c = 0; c < 4; c++) acc[a][b][c] = 0.f;

    const int g = lane >> 3, lr = lane & 7;
    const int a_row  = ((g & 1) << 3) + lr;
    const int a_xtra = (g & 2) ? 16 : 0;
    const int b_row  = ((g >> 1) << 3) + lr;
    const int b_xtra = (g & 1) ? 16 : 0;

    const int pf_row = tid >> 3;
    const int pf_c16 = tid & 7;

    auto prefetch = [&](int kc, int stg) {
        const int kb = kc * 64;
        const uint32_t sb = base + stg * GSTAGE;
#pragma unroll
        for (int i = 0; i < 8; i++) {
            int row = pf_row + i * 16;
            uint32_t so = (uint32_t)(row * GP + pf_c16 * 16);
            CP_ASYNC16(sb + so,         __cvta_generic_to_global(A + (size_t)(m0 + row) * EE + kb + pf_c16 * 8));
            CP_ASYNC16(sb + GTILE + so, __cvta_generic_to_global(B + (size_t)(n0 + row) * EE + kb + pf_c16 * 8));
        }
    };

    prefetch(0, 0); CP_COMMIT();

    int stg = 0;
    for (int kc = 0; kc < KC_N; kc++) {
        CP_WAIT0();
        __syncthreads();
        if (kc + 1 < KC_N) { prefetch(kc + 1, stg ^ 1); CP_COMMIT(); }

        const uint32_t sb = base + stg * GSTAGE;
#pragma unroll
        for (int t = 0; t < 4; t++) {
            uint32_t af[16];
#pragma unroll
            for (int mi = 0; mi < 4; mi++)
                ldmx4(af + mi*4, sb + (uint32_t)((wm + mi*16 + a_row) * GP + t*32 + a_xtra));
#pragma unroll
            for (int np = 0; np < 4; np++) {
                uint32_t bf[4];
                ldmx4(bf, sb + GTILE + (uint32_t)((wn + np*16 + b_row) * GP + t*32 + b_xtra));
#pragma unroll
                for (int mi = 0; mi < 4; mi++) {
                    mma_f16(acc[mi][2*np + 0], af + mi*4, bf + 0);
                    mma_f16(acc[mi][2*np + 1], af + mi*4, bf + 2);
                }
            }
        }
        stg ^= 1;
    }

    // epilogue
#pragma unroll
    for (int mi = 0; mi < 4; mi++) {
        int mrow = m0 + wm + mi*16 + (lane >> 2);
#pragma unroll
        for (int half = 0; half < 2; half++) {
            int m = mrow + half * 8;
#pragma unroll
            for (int ni = 0; ni < 8; ni++) {
                int n = n0 + wn + ni*8 + (lane & 3)*2;
                float v0 = acc[mi][ni][half*2 + 0];
                float v1 = acc[mi][ni][half*2 + 1];
                if (MODE == 1) {
                    *(float2*)(C + (size_t)m * EE + n) = make_float2(v0, v1);
                } else {
                    int s = n >> 10, h = (n >> 6) & 15, d = n & 63;
                    int bidx = m >> 12, l = m & 4095;
                    float r0, r1;
                    if (s == 0) {
                        r0 = (v0 > 0.f ? v0 + 1.f : expf(v0)) * 0.125f;
                        r1 = (v1 > 0.f ? v1 + 1.f : expf(v1)) * 0.125f;
                    } else if (s == 1) {
                        r0 = (v0 > 0.f ? v0 + 1.f : expf(v0));
                        r1 = (v1 > 0.f ? v1 + 1.f : expf(v1));
                    } else {
                        r0 = v0; r1 = v1;
                    }
                    __half* dst = (s == 0) ? g_qh : (s == 1) ? g_kh : g_vh;
                    size_t off = ((size_t)(bidx*HH + h) * LL + l) * DH + d;
                    *(uint32_t*)(dst + off) = packh2(r0, r1);
                }
            }
        }
    }
}

// ---------------- per-chunk Gram via HMMA: G = K_c^T V_c (64x64, k=256), z = sum K_c ----------------
// A = K^T (trans-A ldmatrix), B = V^T (trans-B ldmatrix). 4 warps: warp w owns d-rows [16w,16w+16).
#define KP 144
#define CKV_K_O 0
#define CKV_V_O (256*KP)          // 36864
#define CKV_SMEM (2*256*KP)       // 73728

__global__ __launch_bounds__(128, 3)
void chunk_kv_kernel()
{
    const int c = blockIdx.x, h = blockIdx.y, b = blockIdx.z;
    const int bh = b * HH + h;
    const size_t tokbase = ((size_t)bh * LL + c * CH) * DH;
    const __half* kh = g_kh + tokbase;
    const __half* vh = g_vh + tokbase;

    extern __shared__ char sm[];
    const uint32_t sbase = smem_u32(sm);

    const int tid = threadIdx.x;
    const int w = tid >> 5;
    const int lane = tid & 31;
    const int g = lane >> 3, lr = lane & 7;
    // trans-A (K^T): group g -> K rows ((g>>1)*8 + lr), col bytes (g&1)*16
    const int ka_row  = ((g >> 1) << 3) + lr;
    const int ka_xtra = (g & 1) * 16;
    // trans-B (V^T): lanes 0-15 rows l0-15 col +0; 16-31 col +16B
    const int vt_row = lane & 15;
    const int vt_cb  = (lane >> 4) << 4;

    // load K and V tiles (256 x 64 halves each), pitch 144
#pragma unroll
    for (int t = 0; t < 16; t++) {
        int idx = tid + t * 128;          // 0..2047 uint4 slots
        int row = idx >> 3, c16 = idx & 7;
        uint32_t so = (uint32_t)(row * KP + c16 * 16);
        *(uint4*)(sm + CKV_K_O + so) = *(const uint4*)(kh + (size_t)row * DH + c16 * 8);
        *(uint4*)(sm + CKV_V_O + so) = *(const uint4*)(vh + (size_t)row * DH + c16 * 8);
    }
    __syncthreads();

    float acc[8][4];
#pragma unroll
    for (int ni = 0; ni < 8; ni++)
#pragma unroll
        for (int e = 0; e < 4; e++) acc[ni][e] = 0.f;

#pragma unroll
    for (int t = 0; t < 16; t++) {
        uint32_t af[4];
        ldmx4t(af, sbase + CKV_K_O + (uint32_t)((t*16 + ka_row) * KP + w*32 + ka_xtra));
        uint32_t vb[16];
#pragma unroll
        for (int np = 0; np < 4; np++)
            ldmx4t(vb + np*4, sbase + CKV_V_O + (uint32_t)((t*16 + vt_row) * KP + np*32 + vt_cb));
#pragma unroll
        for (int ni = 0; ni < 8; ni++)
            mma_f16(acc[ni], af, &vb[(ni >> 1)*4 + (ni & 1)*2]);
    }

    // store G fp32 [d][e]
    float* Gout = g_G + ((size_t)bh * NCH + c) * DH * DH;
#pragma unroll
    for (int half = 0; half < 2; half++) {
        int d = w*16 + (lane >> 2) + half*8;
#pragma unroll
        for (int ni = 0; ni < 8; ni++) {
            int e = ni*8 + (lane & 3)*2;
            *(float2*)(Gout + d*DH + e) =
                make_float2(acc[ni][half*2 + 0], acc[ni][half*2 + 1]);
        }
    }

    // z = column sums of K (64 outputs)
    if (tid < DH) {
        float zacc = 0.f;
        const char* kp = sm + CKV_K_O + tid*2;
#pragma unroll 8
        for (int l = 0; l < 256; l++)
            zacc += __half2float(*(const __half*)(kp + l*KP));
        g_zc[((size_t)bh * NCH + c) * DH + tid] = zacc;
    }
}

// ---------------- exclusive prefix over chunks; emits S^T as fp16 ----------------
__global__ __launch_bounds__(256)
void prefix_kernel()
{
    const int bh = blockIdx.x;
    const int tid = threadIdx.x;
    for (int idx = tid; idx < DH*DH; idx += 256) {
        int d = idx >> 6, e = idx & 63;
        float run = 0.f;
        for (int c = 0; c < NCH; c++) {
            size_t gbase = ((size_t)bh * NCH + c) * DH * DH;
            g_STh[gbase + e*DH + d] = __float2half_rn(run);
            run += g_G[gbase + idx];
        }
    }
    if (tid < DH) {
        float run = 0.f;
        for (int c = 0; c < NCH; c++) {
            size_t o = ((size_t)bh * NCH + c) * DH + tid;
            g_Z[o] = run;
            run += g_zc[o];
        }
    }
}

// ---------------- attention core (fp16 HMMA): per (b,h,c,rh), 128x64 tile ----------------
#define AP 144
#define QH_O  0
#define KH_O  18432
#define VH_O  27648
#define ST_O  36864
#define Z_O   46080
#define ATTN_SMEM (Z_O + 256)

__global__ __launch_bounds__(128, 3)
void attn_core_kernel()
{
    const int cc = blockIdx.x;
    const int c = cc >> 1, rh = cc & 1;
    const int h = blockIdx.y, b = blockIdx.z;
    const int bh = b * HH + h;
    const size_t tokbase = (size_t)bh * LL + c * CH;
    const int rowbase = rh * 128;

    extern __shared__ char sm[];
    const uint32_t sbase = smem_u32(sm);

    const int tid = threadIdx.x;
    const int w = tid >> 5;
    const int lane = tid & 31;
    const int g = lane >> 3, lr = lane & 7;
    const int a_row  = ((g & 1) << 3) + lr;
    const int a_xtra = (g & 2) ? 16 : 0;
    const int b_row  = ((g >> 1) << 3) + lr;
    const int b_xtra = (g & 1) ? 16 : 0;
    const int vt_row = lane & 15;
    const int vt_cb  = (lane >> 4) << 4;

    // load Q (128 rows x 64)
    {
        const __half* qh = g_qh + (tokbase + rowbase) * DH;
#pragma unroll
        for (int t = 0; t < 8; t++) {
            int idx = tid + t * 128;
            int row = idx >> 3, c16 = idx & 7;
            *(uint4*)(sm + QH_O + row*AP + c16*16) = *(const uint4*)(qh + (size_t)row*DH + c16*8);
        }
    }
    // load S^T (64x64) + Z
    {
        const size_t stb = ((size_t)bh * NCH + c) * DH * DH;
#pragma unroll
        for (int t = 0; t < 4; t++) {
            int idx = tid + t * 128;
            int row = idx >> 3, c16 = idx & 7;
            *(uint4*)(sm + ST_O + row*AP + c16*16) = *(const uint4*)(g_STh + stb + (size_t)row*DH + c16*8);
        }
        if (tid < DH) *(float*)(sm + Z_O + tid*4) = g_Z[((size_t)bh * NCH + c) * DH + tid];
    }

    float num[2][8][4];
#pragma unroll
    for (int mi = 0; mi < 2; mi++)
#pragma unroll
        for (int ni = 0; ni < 8; ni++)
#pragma unroll
            for (int e = 0; e < 4; e++) num[mi][ni][e] = 0.f;
    float den[2][2] = {{0.f, 0.f}, {0.f, 0.f}};

    const int jb_max = rh * 2 + 2;
    for (int jb = 0; jb < jb_max; jb++) {
        __syncthreads();
        {
            const __half* kh = g_kh + (tokbase + jb*64) * DH;
            const __half* vh = g_vh + (tokbase + jb*64) * DH;
#pragma unroll
            for (int t = 0; t < 4; t++) {
                int idx = tid + t * 128;
                int row = idx >> 3, c16 = idx & 7;
                *(uint4*)(sm + KH_O + row*AP + c16*16) = *(const uint4*)(kh + (size_t)row*DH + c16*8);
                *(uint4*)(sm + VH_O + row*AP + c16*16) = *(const uint4*)(vh + (size_t)row*DH + c16*8);
            }
        }
        __syncthreads();

        // GEMM1: P = Q_half * Kstrip^T
        float pacc[2][8][4];
#pragma unroll
        for (int mi = 0; mi < 2; mi++)
#pragma unroll
            for (int ni = 0; ni < 8; ni++)
#pragma unroll
                for (int e = 0; e < 4; e++) pacc[mi][ni][e] = 0.f;

#pragma unroll
        for (int t = 0; t < 4; t++) {
            uint32_t kb[16];
#pragma unroll
            for (int np = 0; np < 4; np++)
                ldmx4(kb + np*4, sbase + KH_O + (uint32_t)((np*16 + b_row)*AP + t*32 + b_xtra));
#pragma unroll
            for (int mi = 0; mi < 2; mi++) {
                uint32_t ah[4];
                ldmx4(ah, sbase + QH_O + (uint32_t)((w*32 + mi*16 + a_row)*AP + t*32 + a_xtra));
#pragma unroll
                for (int ni = 0; ni < 8; ni++)
                    mma_f16(pacc[mi][ni], ah, &kb[(ni >> 1)*4 + (ni & 1)*2]);
            }
        }

        // causal mask + den partials
#pragma unroll
        for (int mi = 0; mi < 2; mi++)
#pragma unroll
            for (int ni = 0; ni < 8; ni++)
#pragma unroll
                for (int e = 0; e < 4; e++) {
                    int row = rowbase + w*32 + mi*16 + (lane >> 2) + (e >> 1)*8;
                    int col = jb*64 + ni*8 + (lane & 3)*2 + (e & 1);
                    if (col > row) pacc[mi][ni][e] = 0.f;
                    else           den[mi][e >> 1] += pacc[mi][ni][e];
                }

        // GEMM2: num += P * Vstrip
#pragma unroll
        for (int t = 0; t < 4; t++) {
            uint32_t vb[16];
#pragma unroll
            for (int np = 0; np < 4; np++)
                ldmx4t(vb + np*4, sbase + VH_O +
                       (uint32_t)((t*16 + vt_row)*AP + np*32 + vt_cb));
#pragma unroll
            for (int mi = 0; mi < 2; mi++) {
                uint32_t ph[4];
                ph[0] = packh2(pacc[mi][2*t][0],   pacc[mi][2*t][1]);
                ph[1] = packh2(pacc[mi][2*t][2],   pacc[mi][2*t][3]);
                ph[2] = packh2(pacc[mi][2*t+1][0], pacc[mi][2*t+1][1]);
                ph[3] = packh2(pacc[mi][2*t+1][2], pacc[mi][2*t+1][3]);
#pragma unroll
                for (int ni = 0; ni < 8; ni++)
                    mma_f16(num[mi][ni], ph, &vb[(ni >> 1)*4 + (ni & 1)*2]);
            }
        }
    }

    // inter-chunk: num += Q * S
#pragma unroll
    for (int t = 0; t < 4; t++) {
        uint32_t sb[16];
#pragma unroll
        for (int np = 0; np < 4; np++)
            ldmx4(sb + np*4, sbase + ST_O + (uint32_t)((np*16 + b_row)*AP + t*32 + b_xtra));
#pragma unroll
        for (int mi = 0; mi < 2; mi++) {
            uint32_t ah[4];
            ldmx4(ah, sbase + QH_O + (uint32_t)((w*32 + mi*16 + a_row)*AP + t*32 + a_xtra));
#pragma unroll
            for (int ni = 0; ni < 8; ni++)
                mma_f16(num[mi][ni], ah, &sb[(ni >> 1)*4 + (ni & 1)*2]);
        }
    }

    // den: quad reduce, then + q.Z
#pragma unroll
    for (int mi = 0; mi < 2; mi++)
#pragma unroll
        for (int hf = 0; hf < 2; hf++) {
            float d = den[mi][hf];
            d += __shfl_xor_sync(0xffffffffu, d, 1);
            d += __shfl_xor_sync(0xffffffffu, d, 2);
            int row = w*32 + mi*16 + (lane >> 2) + hf*8;
            float qz = 0.f;
            const char* qr = sm + QH_O + row*AP;
#pragma unroll
            for (int dd = 0; dd < 32; dd++) {
                float2 q2 = __half22float2(*(const __half2*)(qr + dd*4));
                float2 z2 = *(const float2*)(sm + Z_O + dd*8);
                qz += q2.x * z2.x + q2.y * z2.y;
            }
            den[mi][hf] = d + qz;
        }

    // divide + fp16 store
    const size_t mbase = (size_t)(b * LL + c * CH) + rowbase;
#pragma unroll
    for (int mi = 0; mi < 2; mi++)
#pragma unroll
        for (int hf = 0; hf < 2; hf++) {
            int row = w*32 + mi*16 + (lane >> 2) + hf*8;
            float inv = 1.f / fmaxf(den[mi][hf], 1e-6f);
            size_t ob = (mbase + row) * EE + h * DH;
#pragma unroll
            for (int ni = 0; ni < 8; ni++) {
                int e = ni*8 + (lane & 3)*2;
                *(uint32_t*)(g_atth + ob + e) =
                    packh2(num[mi][ni][hf*2 + 0] * inv, num[mi][ni][hf*2 + 1] * inv);
            }
        }
}

// ---------------- launch ----------------
extern "C" void kernel_launch(void* const* d_in, const int* in_sizes, int n_in,
                              void* d_out, int out_size)
{
    const float* x    = (const float*)d_in[0];   // [B, L, E]
    const float* Wqkv = (const float*)d_in[1];   // [3E, E]
    const float* Wout = (const float*)d_in[2];   // [E, E]
    float* out = (float*)d_out;                  // [B, L, E]

    cudaFuncSetAttribute(attn_core_kernel,
                         cudaFuncAttributeMaxDynamicSharedMemorySize, ATTN_SMEM);
    cudaFuncSetAttribute(chunk_kv_kernel,
                         cudaFuncAttributeMaxDynamicSharedMemorySize, CKV_SMEM);
    cudaFuncSetAttribute(hmma_gemm_kernel<0>,
                         cudaFuncAttributeMaxDynamicSharedMemorySize, GSMEM);
    cudaFuncSetAttribute(hmma_gemm_kernel<1>,
                         cudaFuncAttributeMaxDynamicSharedMemorySize, GSMEM);

    // 0) fp16 conversion of all inputs (one launch)
    convert_all_kernel<<<(N4_TOT + 255)/256, 256>>>(x, Wqkv, Wout);

    // 1) QKV GEMM + feature-map -> fp16 q/k/v
    {
        dim3 grid(NQKV/128, M1/128);  // (24, 64)
        hmma_gemm_kernel<0><<<grid, 128, GSMEM>>>(nullptr);
    }
    // 2) per-chunk Gram matrices (HMMA)
    {
        dim3 grid(NCH, HH, BB);
        chunk_kv_kernel<<<grid, 128, CKV_SMEM>>>();
    }
    // 3) exclusive prefix (emits S^T fp16 + Z)
    prefix_kernel<<<BB*HH, 256>>>();
    // 4) attention core (fp16 HMMA, 128-row half-tiles, causal strip-skip)
    {
        dim3 grid(NCH*2, HH, BB);
        attn_core_kernel<<<grid, 128, ATTN_SMEM>>>();
    }
    // 5) output GEMM: out = att @ Wout^T
    {
        dim3 grid(EE/128, M1/128);    // (8, 64)
        hmma_gemm_kernel<1><<<grid, 128, GSMEM>>>(out);
    }
}

// round 14
// speedup vs baseline: 1.5473x; 1.2091x over previous
#include <cuda_runtime.h>
#include <cuda_fp16.h>
#include <math.h>
#include <stdint.h>

#define BB 2
#define LL 4096
#define EE 1024
#define HH 16
#define DH 64
#define CH 256
#define NCH 16
#define M1 (BB*LL)      // 8192
#define NQKV (3*EE)     // 3072

// ---------------- scratch (static device globals; no allocation) ----------------
__device__ __align__(16) __half g_xh[(size_t)M1*EE];
__device__ __align__(16) __half g_wqkvh[(size_t)NQKV*EE];
__device__ __align__(16) __half g_wouth[(size_t)EE*EE];
__device__ __align__(16) __half g_atth[(size_t)M1*EE];

__device__ __align__(16) __half g_qh[(size_t)BB*HH*LL*DH];
__device__ __align__(16) __half g_kh[(size_t)BB*HH*LL*DH];
__device__ __align__(16) __half g_vh[(size_t)BB*HH*LL*DH];

__device__ float g_G[(size_t)BB*HH*NCH*DH*DH];
__device__ __align__(16) __half g_STh[(size_t)BB*HH*NCH*DH*DH];
__device__ float g_zc[(size_t)BB*HH*NCH*DH];
__device__ float g_Z[(size_t)BB*HH*NCH*DH];

// ---------------- helpers ----------------
__device__ __forceinline__ uint32_t smem_u32(const void* p) {
    uint32_t a;
    asm("{ .reg .u64 t; cvta.to.shared.u64 t, %1; cvt.u32.u64 %0, t; }" : "=r"(a) : "l"(p));
    return a;
}
__device__ __forceinline__ void ldmx4(uint32_t* r, uint32_t a) {
    asm volatile("ldmatrix.sync.aligned.m8n8.x4.shared.b16 {%0,%1,%2,%3}, [%4];"
        : "=r"(r[0]), "=r"(r[1]), "=r"(r[2]), "=r"(r[3]) : "r"(a));
}
__device__ __forceinline__ void ldmx4t(uint32_t* r, uint32_t a) {
    asm volatile("ldmatrix.sync.aligned.m8n8.x4.trans.shared.b16 {%0,%1,%2,%3}, [%4];"
        : "=r"(r[0]), "=r"(r[1]), "=r"(r[2]), "=r"(r[3]) : "r"(a));
}
__device__ __forceinline__ void mma_f16(float* d, const uint32_t* a, const uint32_t* b) {
    asm volatile(
        "mma.sync.aligned.m16n8k16.row.col.f32.f16.f16.f32 "
        "{%0,%1,%2,%3}, {%4,%5,%6,%7}, {%8,%9}, {%0,%1,%2,%3};"
        : "+f"(d[0]), "+f"(d[1]), "+f"(d[2]), "+f"(d[3])
        : "r"(a[0]), "r"(a[1]), "r"(a[2]), "r"(a[3]), "r"(b[0]), "r"(b[1]));
}
__device__ __forceinline__ uint32_t packh2(float a, float b) {
    __half2 t = __halves2half2(__float2half_rn(a), __float2half_rn(b));
    return *(uint32_t*)&t;
}

#define CP_ASYNC16(s, g) \
    asm volatile("cp.async.cg.shared.global [%0], [%1], 16;" :: "r"(s), "l"(g))
#define CP_COMMIT() asm volatile("cp.async.commit_group;")
#define CP_WAIT0()  asm volatile("cp.async.wait_group 0;")

// ---------------- fp32 -> fp16 converter (all three inputs, one launch) ----------------
#define N4_X    (M1*EE/4)      // 2097152
#define N4_WQKV (NQKV*EE/4)    // 786432
#define N4_WOUT (EE*EE/4)      // 262144
#define N4_TOT  (N4_X + N4_WQKV + N4_WOUT)

__global__ __launch_bounds__(256)
void convert_all_kernel(const float* __restrict__ x,
                        const float* __restrict__ wqkv,
                        const float* __restrict__ wout)
{
    int i = blockIdx.x * 256 + threadIdx.x;
    if (i >= N4_TOT) return;
    const float* src;
    __half* dst;
    int j = i;
    if (j < N4_X)                { src = x;    dst = g_xh; }
    else if ((j -= N4_X) < N4_WQKV) { src = wqkv; dst = g_wqkvh; }
    else { j -= N4_WQKV;           src = wout; dst = g_wouth; }
    float4 v = ((const float4*)src)[j];
    ((__half2*)dst)[j*2 + 0] = __halves2half2(__float2half_rn(v.x), __float2half_rn(v.y));
    ((__half2*)dst)[j*2 + 1] = __halves2half2(__float2half_rn(v.z), __float2half_rn(v.w));
}

// ---------------- fp16 HMMA GEMM (unchanged — best known) ----------------
#define GP 144
#define GTILE (128*GP)       // 18432
#define GSTAGE (2*GTILE)     // 36864 (A + B)
#define GSMEM (2*GSTAGE)     // 73728
#define KC_N 16              // 1024 / 64

template<int MODE>
__global__ __launch_bounds__(128, 3)
void hmma_gemm_kernel(float* __restrict__ C)
{
    const __half* __restrict__ A = (MODE == 0) ? g_xh : g_atth;
    const __half* __restrict__ B = (MODE == 0) ? g_wqkvh : g_wouth;

    const int m0 = blockIdx.y * 128;
    const int n0 = blockIdx.x * 128;
    const int tid = threadIdx.x;
    const int wid = tid >> 5;
    const int lane = tid & 31;
    const int wm = (wid >> 1) * 64;
    const int wn = (wid & 1) * 64;

    extern __shared__ char smc[];
    const uint32_t base = smem_u32(smc);

    float acc[4][8][4];
#pragma unroll
    for (int a = 0; a < 4; a++)
#pragma unroll
        for (int b = 0; b < 8; b++)
#pragma unroll
            for (int c = 0; c < 4; c++) acc[a][b][c] = 0.f;

    const int g = lane >> 3, lr = lane & 7;
    const int a_row  = ((g & 1) << 3) + lr;
    const int a_xtra = (g & 2) ? 16 : 0;
    const int b_row  = ((g >> 1) << 3) + lr;
    const int b_xtra = (g & 1) ? 16 : 0;

    const int pf_row = tid >> 3;
    const int pf_c16 = tid & 7;

    auto prefetch = [&](int kc, int stg) {
        const int kb = kc * 64;
        const uint32_t sb = base + stg * GSTAGE;
#pragma unroll
        for (int i = 0; i < 8; i++) {
            int row = pf_row + i * 16;
            uint32_t so = (uint32_t)(row * GP + pf_c16 * 16);
            CP_ASYNC16(sb + so,         __cvta_generic_to_global(A + (size_t)(m0 + row) * EE + kb + pf_c16 * 8));
            CP_ASYNC16(sb + GTILE + so, __cvta_generic_to_global(B + (size_t)(n0 + row) * EE + kb + pf_c16 * 8));
        }
    };

    prefetch(0, 0); CP_COMMIT();

    int stg = 0;
    for (int kc = 0; kc < KC_N; kc++) {
        CP_WAIT0();
        __syncthreads();
        if (kc + 1 < KC_N) { prefetch(kc + 1, stg ^ 1); CP_COMMIT(); }

        const uint32_t sb = base + stg * GSTAGE;
#pragma unroll
        for (int t = 0; t < 4; t++) {
            uint32_t af[16];
#pragma unroll
            for (int mi = 0; mi < 4; mi++)
                ldmx4(af + mi*4, sb + (uint32_t)((wm + mi*16 + a_row) * GP + t*32 + a_xtra));
#pragma unroll
            for (int np = 0; np < 4; np++) {
                uint32_t bf[4];
                ldmx4(bf, sb + GTILE + (uint32_t)((wn + np*16 + b_row) * GP + t*32 + b_xtra));
#pragma unroll
                for (int mi = 0; mi < 4; mi++) {
                    mma_f16(acc[mi][2*np + 0], af + mi*4, bf + 0);
                    mma_f16(acc[mi][2*np + 1], af + mi*4, bf + 2);
                }
            }
        }
        stg ^= 1;
    }

    // epilogue
#pragma unroll
    for (int mi = 0; mi < 4; mi++) {
        int mrow = m0 + wm + mi*16 + (lane >> 2);
#pragma unroll
        for (int half = 0; half < 2; half++) {
            int m = mrow + half * 8;
#pragma unroll
            for (int ni = 0; ni < 8; ni++) {
                int n = n0 + wn + ni*8 + (lane & 3)*2;
                float v0 = acc[mi][ni][half*2 + 0];
                float v1 = acc[mi][ni][half*2 + 1];
                if (MODE == 1) {
                    *(float2*)(C + (size_t)m * EE + n) = make_float2(v0, v1);
                } else {
                    int s = n >> 10, h = (n >> 6) & 15, d = n & 63;
                    int bidx = m >> 12, l = m & 4095;
                    float r0, r1;
                    if (s == 0) {
                        r0 = (v0 > 0.f ? v0 + 1.f : expf(v0)) * 0.125f;
                        r1 = (v1 > 0.f ? v1 + 1.f : expf(v1)) * 0.125f;
                    } else if (s == 1) {
                        r0 = (v0 > 0.f ? v0 + 1.f : expf(v0));
                        r1 = (v1 > 0.f ? v1 + 1.f : expf(v1));
                    } else {
                        r0 = v0; r1 = v1;
                    }
                    __half* dst = (s == 0) ? g_qh : (s == 1) ? g_kh : g_vh;
                    size_t off = ((size_t)(bidx*HH + h) * LL + l) * DH + d;
                    *(uint32_t*)(dst + off) = packh2(r0, r1);
                }
            }
        }
    }
}

// ---------------- per-chunk Gram via HMMA: G = K_c^T V_c (64x64, k=256), z = sum K_c ----------------
#define KP 144
#define CKV_K_O 0
#define CKV_V_O (256*KP)          // 36864
#define CKV_SMEM (2*256*KP)       // 73728

__global__ __launch_bounds__(128, 3)
void chunk_kv_kernel()
{
    const int c = blockIdx.x, h = blockIdx.y, b = blockIdx.z;
    const int bh = b * HH + h;
    const size_t tokbase = ((size_t)bh * LL + c * CH) * DH;
    const __half* kh = g_kh + tokbase;
    const __half* vh = g_vh + tokbase;

    extern __shared__ char sm[];
    const uint32_t sbase = smem_u32(sm);

    const int tid = threadIdx.x;
    const int w = tid >> 5;
    const int lane = tid & 31;
    const int g = lane >> 3, lr = lane & 7;
    const int ka_row  = ((g >> 1) << 3) + lr;
    const int ka_xtra = (g & 1) * 16;
    const int vt_row = lane & 15;
    const int vt_cb  = (lane >> 4) << 4;

#pragma unroll
    for (int t = 0; t < 16; t++) {
        int idx = tid + t * 128;
        int row = idx >> 3, c16 = idx & 7;
        uint32_t so = (uint32_t)(row * KP + c16 * 16);
        *(uint4*)(sm + CKV_K_O + so) = *(const uint4*)(kh + (size_t)row * DH + c16 * 8);
        *(uint4*)(sm + CKV_V_O + so) = *(const uint4*)(vh + (size_t)row * DH + c16 * 8);
    }
    __syncthreads();

    float acc[8][4];
#pragma unroll
    for (int ni = 0; ni < 8; ni++)
#pragma unroll
        for (int e = 0; e < 4; e++) acc[ni][e] = 0.f;

#pragma unroll
    for (int t = 0; t < 16; t++) {
        uint32_t af[4];
        ldmx4t(af, sbase + CKV_K_O + (uint32_t)((t*16 + ka_row) * KP + w*32 + ka_xtra));
        uint32_t vb[16];
#pragma unroll
        for (int np = 0; np < 4; np++)
            ldmx4t(vb + np*4, sbase + CKV_V_O + (uint32_t)((t*16 + vt_row) * KP + np*32 + vt_cb));
#pragma unroll
        for (int ni = 0; ni < 8; ni++)
            mma_f16(acc[ni], af, &vb[(ni >> 1)*4 + (ni & 1)*2]);
    }

    float* Gout = g_G + ((size_t)bh * NCH + c) * DH * DH;
#pragma unroll
    for (int half = 0; half < 2; half++) {
        int d = w*16 + (lane >> 2) + half*8;
#pragma unroll
        for (int ni = 0; ni < 8; ni++) {
            int e = ni*8 + (lane & 3)*2;
            *(float2*)(Gout + d*DH + e) =
                make_float2(acc[ni][half*2 + 0], acc[ni][half*2 + 1]);
        }
    }

    if (tid < DH) {
        float zacc = 0.f;
        const char* kp = sm + CKV_K_O + tid*2;
#pragma unroll 8
        for (int l = 0; l < 256; l++)
            zacc += __half2float(*(const __half*)(kp + l*KP));
        g_zc[((size_t)bh * NCH + c) * DH + tid] = zacc;
    }
}

// ---------------- exclusive prefix over chunks (parallel, latency-batched) ----------------
// grid (16, 32): y = bh, x covers the 4096 (d,e) elements in 256-thread slabs.
// All 16 G loads issued up-front (MLP=16), prefix in registers, fp16 stores fire-and-forget.
__global__ __launch_bounds__(256)
void prefix_kernel()
{
    const int bh = blockIdx.y;
    const int idx = blockIdx.x * 256 + threadIdx.x;   // 0..4095
    const int d = idx >> 6, e = idx & 63;
    const size_t gb = (size_t)bh * NCH * DH * DH;

    float gv[NCH];
#pragma unroll
    for (int c = 0; c < NCH; c++)
        gv[c] = g_G[gb + (size_t)c * DH * DH + idx];

    float run = 0.f;
#pragma unroll
    for (int c = 0; c < NCH; c++) {
        g_STh[gb + (size_t)c * DH * DH + e * DH + d] = __float2half_rn(run);
        run += gv[c];
    }

    // z prefix: one slab per bh handles the 64 columns
    if (blockIdx.x == 0 && threadIdx.x < DH) {
        const size_t zb = (size_t)bh * NCH * DH;
        float zv[NCH];
#pragma unroll
        for (int c = 0; c < NCH; c++)
            zv[c] = g_zc[zb + (size_t)c * DH + threadIdx.x];
        float zr = 0.f;
#pragma unroll
        for (int c = 0; c < NCH; c++) {
            g_Z[zb + (size_t)c * DH + threadIdx.x] = zr;
            zr += zv[c];
        }
    }
}

// ---------------- attention core (fp16 HMMA): per (b,h,c,rh), 128x64 tile ----------------
#define AP 144
#define QH_O  0
#define KH_O  18432
#define VH_O  27648
#define ST_O  36864
#define Z_O   46080
#define ATTN_SMEM (Z_O + 256)

__global__ __launch_bounds__(128, 3)
void attn_core_kernel()
{
    const int cc = blockIdx.x;
    const int c = cc >> 1, rh = cc & 1;
    const int h = blockIdx.y, b = blockIdx.z;
    const int bh = b * HH + h;
    const size_t tokbase = (size_t)bh * LL + c * CH;
    const int rowbase = rh * 128;

    extern __shared__ char sm[];
    const uint32_t sbase = smem_u32(sm);

    const int tid = threadIdx.x;
    const int w = tid >> 5;
    const int lane = tid & 31;
    const int g = lane >> 3, lr = lane & 7;
    const int a_row  = ((g & 1) << 3) + lr;
    const int a_xtra = (g & 2) ? 16 : 0;
    const int b_row  = ((g >> 1) << 3) + lr;
    const int b_xtra = (g & 1) ? 16 : 0;
    const int vt_row = lane & 15;
    const int vt_cb  = (lane >> 4) << 4;

    // load Q (128 rows x 64)
    {
        const __half* qh = g_qh + (tokbase + rowbase) * DH;
#pragma unroll
        for (int t = 0; t < 8; t++) {
            int idx = tid + t * 128;
            int row = idx >> 3, c16 = idx & 7;
            *(uint4*)(sm + QH_O + row*AP + c16*16) = *(const uint4*)(qh + (size_t)row*DH + c16*8);
        }
    }
    // load S^T (64x64) + Z
    {
        const size_t stb = ((size_t)bh * NCH + c) * DH * DH;
#pragma unroll
        for (int t = 0; t < 4; t++) {
            int idx = tid + t * 128;
            int row = idx >> 3, c16 = idx & 7;
            *(uint4*)(sm + ST_O + row*AP + c16*16) = *(const uint4*)(g_STh + stb + (size_t)row*DH + c16*8);
        }
        if (tid < DH) *(float*)(sm + Z_O + tid*4) = g_Z[((size_t)bh * NCH + c) * DH + tid];
    }

    float num[2][8][4];
#pragma unroll
    for (int mi = 0; mi < 2; mi++)
#pragma unroll
        for (int ni = 0; ni < 8; ni++)
#pragma unroll
            for (int e = 0; e < 4; e++) num[mi][ni][e] = 0.f;
    float den[2][2] = {{0.f, 0.f}, {0.f, 0.f}};

    const int jb_max = rh * 2 + 2;
    for (int jb = 0; jb < jb_max; jb++) {
        __syncthreads();
        {
            const __half* kh = g_kh + (tokbase + jb*64) * DH;
            const __half* vh = g_vh + (tokbase + jb*64) * DH;
#pragma unroll
            for (int t = 0; t < 4; t++) {
                int idx = tid + t * 128;
                int row = idx >> 3, c16 = idx & 7;
                *(uint4*)(sm + KH_O + row*AP + c16*16) = *(const uint4*)(kh + (size_t)row*DH + c16*8);
                *(uint4*)(sm + VH_O + row*AP + c16*16) = *(const uint4*)(vh + (size_t)row*DH + c16*8);
            }
        }
        __syncthreads();

        // GEMM1: P = Q_half * Kstrip^T
        float pacc[2][8][4];
#pragma unroll
        for (int mi = 0; mi < 2; mi++)
#pragma unroll
            for (int ni = 0; ni < 8; ni++)
#pragma unroll
                for (int e = 0; e < 4; e++) pacc[mi][ni][e] = 0.f;

#pragma unroll
        for (int t = 0; t < 4; t++) {
            uint32_t kb[16];
#pragma unroll
            for (int np = 0; np < 4; np++)
                ldmx4(kb + np*4, sbase + KH_O + (uint32_t)((np*16 + b_row)*AP + t*32 + b_xtra));
#pragma unroll
            for (int mi = 0; mi < 2; mi++) {
                uint32_t ah[4];
                ldmx4(ah, sbase + QH_O + (uint32_t)((w*32 + mi*16 + a_row)*AP + t*32 + a_xtra));
#pragma unroll
                for (int ni = 0; ni < 8; ni++)
                    mma_f16(pacc[mi][ni], ah, &kb[(ni >> 1)*4 + (ni & 1)*2]);
            }
        }

        // causal mask + den partials
#pragma unroll
        for (int mi = 0; mi < 2; mi++)
#pragma unroll
            for (int ni = 0; ni < 8; ni++)
#pragma unroll
                for (int e = 0; e < 4; e++) {
                    int row = rowbase + w*32 + mi*16 + (lane >> 2) + (e >> 1)*8;
                    int col = jb*64 + ni*8 + (lane & 3)*2 + (e & 1);
                    if (col > row) pacc[mi][ni][e] = 0.f;
                    else           den[mi][e >> 1] += pacc[mi][ni][e];
                }

        // GEMM2: num += P * Vstrip
#pragma unroll
        for (int t = 0; t < 4; t++) {
            uint32_t vb[16];
#pragma unroll
            for (int np = 0; np < 4; np++)
                ldmx4t(vb + np*4, sbase + VH_O +
                       (uint32_t)((t*16 + vt_row)*AP + np*32 + vt_cb));
#pragma unroll
            for (int mi = 0; mi < 2; mi++) {
                uint32_t ph[4];
                ph[0] = packh2(pacc[mi][2*t][0],   pacc[mi][2*t][1]);
                ph[1] = packh2(pacc[mi][2*t][2],   pacc[mi][2*t][3]);
                ph[2] = packh2(pacc[mi][2*t+1][0], pacc[mi][2*t+1][1]);
                ph[3] = packh2(pacc[mi][2*t+1][2], pacc[mi][2*t+1][3]);
#pragma unroll
                for (int ni = 0; ni < 8; ni++)
                    mma_f16(num[mi][ni], ph, &vb[(ni >> 1)*4 + (ni & 1)*2]);
            }
        }
    }

    // inter-chunk: num += Q * S
#pragma unroll
    for (int t = 0; t < 4; t++) {
        uint32_t sb[16];
#pragma unroll
        for (int np = 0; np < 4; np++)
            ldmx4(sb + np*4, sbase + ST_O + (uint32_t)((np*16 + b_row)*AP + t*32 + b_xtra));
#pragma unroll
        for (int mi = 0; mi < 2; mi++) {
            uint32_t ah[4];
            ldmx4(ah, sbase + QH_O + (uint32_t)((w*32 + mi*16 + a_row)*AP + t*32 + a_xtra));
#pragma unroll
            for (int ni = 0; ni < 8; ni++)
                mma_f16(num[mi][ni], ah, &sb[(ni >> 1)*4 + (ni & 1)*2]);
        }
    }

    // den: quad reduce, then + q.Z
#pragma unroll
    for (int mi = 0; mi < 2; mi++)
#pragma unroll
        for (int hf = 0; hf < 2; hf++) {
            float d = den[mi][hf];
            d += __shfl_xor_sync(0xffffffffu, d, 1);
            d += __shfl_xor_sync(0xffffffffu, d, 2);
            int row = w*32 + mi*16 + (lane >> 2) + hf*8;
            float qz = 0.f;
            const char* qr = sm + QH_O + row*AP;
#pragma unroll
            for (int dd = 0; dd < 32; dd++) {
                float2 q2 = __half22float2(*(const __half2*)(qr + dd*4));
                float2 z2 = *(const float2*)(sm + Z_O + dd*8);
                qz += q2.x * z2.x + q2.y * z2.y;
            }
            den[mi][hf] = d + qz;
        }

    // divide + fp16 store
    const size_t mbase = (size_t)(b * LL + c * CH) + rowbase;
#pragma unroll
    for (int mi = 0; mi < 2; mi++)
#pragma unroll
        for (int hf = 0; hf < 2; hf++) {
            int row = w*32 + mi*16 + (lane >> 2) + hf*8;
            float inv = 1.f / fmaxf(den[mi][hf], 1e-6f);
            size_t ob = (mbase + row) * EE + h * DH;
#pragma unroll
            for (int ni = 0; ni < 8; ni++) {
                int e = ni*8 + (lane & 3)*2;
                *(uint32_t*)(g_atth + ob + e) =
                    packh2(num[mi][ni][hf*2 + 0] * inv, num[mi][ni][hf*2 + 1] * inv);
            }
        }
}

// ---------------- launch ----------------
extern "C" void kernel_launch(void* const* d_in, const int* in_sizes, int n_in,
                              void* d_out, int out_size)
{
    const float* x    = (const float*)d_in[0];   // [B, L, E]
    const float* Wqkv = (const float*)d_in[1];   // [3E, E]
    const float* Wout = (const float*)d_in[2];   // [E, E]
    float* out = (float*)d_out;                  // [B, L, E]

    cudaFuncSetAttribute(attn_core_kernel,
                         cudaFuncAttributeMaxDynamicSharedMemorySize, ATTN_SMEM);
    cudaFuncSetAttribute(chunk_kv_kernel,
                         cudaFuncAttributeMaxDynamicSharedMemorySize, CKV_SMEM);
    cudaFuncSetAttribute(hmma_gemm_kernel<0>,
                         cudaFuncAttributeMaxDynamicSharedMemorySize, GSMEM);
    cudaFuncSetAttribute(hmma_gemm_kernel<1>,
                         cudaFuncAttributeMaxDynamicSharedMemorySize, GSMEM);

    // 0) fp16 conversion of all inputs (one launch)
    convert_all_kernel<<<(N4_TOT + 255)/256, 256>>>(x, Wqkv, Wout);

    // 1) QKV GEMM + feature-map -> fp16 q/k/v
    {
        dim3 grid(NQKV/128, M1/128);  // (24, 64)
        hmma_gemm_kernel<0><<<grid, 128, GSMEM>>>(nullptr);
    }
    // 2) per-chunk Gram matrices (HMMA)
    {
        dim3 grid(NCH, HH, BB);
        chunk_kv_kernel<<<grid, 128, CKV_SMEM>>>();
    }
    // 3) exclusive prefix (parallel over all elements)
    {
        dim3 grid(DH*DH/256, BB*HH);  // (16, 32)
        prefix_kernel<<<grid, 256>>>();
    }
    // 4) attention core (fp16 HMMA, 128-row half-tiles, causal strip-skip)
    {
        dim3 grid(NCH*2, HH, BB);
        attn_core_kernel<<<grid, 128, ATTN_SMEM>>>();
    }
    // 5) output GEMM: out = att @ Wout^T
    {
        dim3 grid(EE/128, M1/128);    // (8, 64)
        hmma_gemm_kernel<1><<<grid, 128, GSMEM>>>(out);
    }
}

// round 17
// speedup vs baseline: 1.6435x; 1.0622x over previous
#include <cuda_runtime.h>
#include <cuda_fp16.h>
#include <math.h>
#include <stdint.h>

#define BB 2
#define LL 4096
#define EE 1024
#define HH 16
#define DH 64
#define CH 256
#define NCH 16
#define M1 (BB*LL)      // 8192
#define NQKV (3*EE)     // 3072

// ---------------- scratch (static device globals; no allocation) ----------------
__device__ __align__(16) __half g_xh[(size_t)M1*EE];
__device__ __align__(16) __half g_wqkvh[(size_t)NQKV*EE];
__device__ __align__(16) __half g_wouth[(size_t)EE*EE];
__device__ __align__(16) __half g_atth[(size_t)M1*EE];

__device__ __align__(16) __half g_qh[(size_t)BB*HH*LL*DH];
__device__ __align__(16) __half g_kh[(size_t)BB*HH*LL*DH];
__device__ __align__(16) __half g_vh[(size_t)BB*HH*LL*DH];

__device__ float g_G[(size_t)BB*HH*NCH*DH*DH];
__device__ __align__(16) __half g_Sh[(size_t)BB*HH*NCH*DH*DH];   // S prefix, [d][e] fp16
__device__ float g_zc[(size_t)BB*HH*NCH*DH];
__device__ float g_Z[(size_t)BB*HH*NCH*DH];

// ---------------- helpers ----------------
__device__ __forceinline__ uint32_t smem_u32(const void* p) {
    uint32_t a;
    asm("{ .reg .u64 t; cvta.to.shared.u64 t, %1; cvt.u32.u64 %0, t; }" : "=r"(a) : "l"(p));
    return a;
}
__device__ __forceinline__ void ldmx4(uint32_t* r, uint32_t a) {
    asm volatile("ldmatrix.sync.aligned.m8n8.x4.shared.b16 {%0,%1,%2,%3}, [%4];"
        : "=r"(r[0]), "=r"(r[1]), "=r"(r[2]), "=r"(r[3]) : "r"(a));
}
__device__ __forceinline__ void ldmx4t(uint32_t* r, uint32_t a) {
    asm volatile("ldmatrix.sync.aligned.m8n8.x4.trans.shared.b16 {%0,%1,%2,%3}, [%4];"
        : "=r"(r[0]), "=r"(r[1]), "=r"(r[2]), "=r"(r[3]) : "r"(a));
}
__device__ __forceinline__ void mma_f16(float* d, const uint32_t* a, const uint32_t* b) {
    asm volatile(
        "mma.sync.aligned.m16n8k16.row.col.f32.f16.f16.f32 "
        "{%0,%1,%2,%3}, {%4,%5,%6,%7}, {%8,%9}, {%0,%1,%2,%3};"
        : "+f"(d[0]), "+f"(d[1]), "+f"(d[2]), "+f"(d[3])
        : "r"(a[0]), "r"(a[1]), "r"(a[2]), "r"(a[3]), "r"(b[0]), "r"(b[1]));
}
__device__ __forceinline__ uint32_t packh2(float a, float b) {
    __half2 t = __halves2half2(__float2half_rn(a), __float2half_rn(b));
    return *(uint32_t*)&t;
}

#define CP_ASYNC16(s, g) \
    asm volatile("cp.async.cg.shared.global [%0], [%1], 16;" :: "r"(s), "l"(g))
#define CP_COMMIT() asm volatile("cp.async.commit_group;")
#define CP_WAIT0()  asm volatile("cp.async.wait_group 0;")

// ---------------- fp32 -> fp16 converter (all three inputs, one launch) ----------------
#define N4_X    (M1*EE/4)
#define N4_WQKV (NQKV*EE/4)
#define N4_WOUT (EE*EE/4)
#define N4_TOT  (N4_X + N4_WQKV + N4_WOUT)

__global__ __launch_bounds__(256)
void convert_all_kernel(const float* __restrict__ x,
                        const float* __restrict__ wqkv,
                        const float* __restrict__ wout)
{
    int i = blockIdx.x * 256 + threadIdx.x;
    if (i >= N4_TOT) return;
    const float* src;
    __half* dst;
    int j = i;
    if (j < N4_X)                { src = x;    dst = g_xh; }
    else if ((j -= N4_X) < N4_WQKV) { src = wqkv; dst = g_wqkvh; }
    else { j -= N4_WQKV;           src = wout; dst = g_wouth; }
    float4 v = ((const float4*)src)[j];
    ((__half2*)dst)[j*2 + 0] = __halves2half2(__float2half_rn(v.x), __float2half_rn(v.y));
    ((__half2*)dst)[j*2 + 1] = __halves2half2(__float2half_rn(v.z), __float2half_rn(v.w));
}

// ---------------- fp16 HMMA GEMM: 256 thr, 8 warps (2m x 4n), warp 64x32, 2 CTAs/SM ----------------
#define GP 144
#define GTILE (128*GP)       // 18432
#define GSTAGE (2*GTILE)     // 36864 (A + B)
#define GSMEM (2*GSTAGE)     // 73728 -> 2 CTAs/SM
#define KC_N 16              // 1024 / 64

template<int MODE>
__global__ __launch_bounds__(256, 2)
void hmma_gemm_kernel(float* __restrict__ C)
{
    const __half* __restrict__ A = (MODE == 0) ? g_xh : g_atth;
    const __half* __restrict__ B = (MODE == 0) ? g_wqkvh : g_wouth;

    const int m0 = blockIdx.y * 128;
    const int n0 = blockIdx.x * 128;
    const int tid = threadIdx.x;
    const int wid = tid >> 5;
    const int lane = tid & 31;
    const int wm = (wid >> 2) * 64;   // 0, 64
    const int wn = (wid & 3) * 32;    // 0, 32, 64, 96

    extern __shared__ char smc[];
    const uint32_t base = smem_u32(smc);

    float acc[4][4][4];
#pragma unroll
    for (int a = 0; a < 4; a++)
#pragma unroll
        for (int b = 0; b < 4; b++)
#pragma unroll
            for (int c = 0; c < 4; c++) acc[a][b][c] = 0.f;

    const int g = lane >> 3, lr = lane & 7;
    const int a_row  = ((g & 1) << 3) + lr;
    const int a_xtra = (g & 2) ? 16 : 0;
    const int b_row  = ((g >> 1) << 3) + lr;
    const int b_xtra = (g & 1) ? 16 : 0;

    const int pf_row = tid >> 3;      // 0..31
    const int pf_c16 = tid & 7;

    auto prefetch = [&](int kc, int stg) {
        const int kb = kc * 64;
        const uint32_t sb = base + stg * GSTAGE;
#pragma unroll
        for (int i = 0; i < 4; i++) {
            int row = pf_row + i * 32;
            uint32_t so = (uint32_t)(row * GP + pf_c16 * 16);
            CP_ASYNC16(sb + so,         __cvta_generic_to_global(A + (size_t)(m0 + row) * EE + kb + pf_c16 * 8));
            CP_ASYNC16(sb + GTILE + so, __cvta_generic_to_global(B + (size_t)(n0 + row) * EE + kb + pf_c16 * 8));
        }
    };

    prefetch(0, 0); CP_COMMIT();

    int stg = 0;
    for (int kc = 0; kc < KC_N; kc++) {
        CP_WAIT0();
        __syncthreads();
        if (kc + 1 < KC_N) { prefetch(kc + 1, stg ^ 1); CP_COMMIT(); }

        const uint32_t sb = base + stg * GSTAGE;
#pragma unroll
        for (int t = 0; t < 4; t++) {
            uint32_t bf[8];
#pragma unroll
            for (int np = 0; np < 2; np++)
                ldmx4(bf + np*4, sb + GTILE + (uint32_t)((wn + np*16 + b_row) * GP + t*32 + b_xtra));
            uint32_t af[16];
#pragma unroll
            for (int mi = 0; mi < 4; mi++)
                ldmx4(af + mi*4, sb + (uint32_t)((wm + mi*16 + a_row) * GP + t*32 + a_xtra));
#pragma unroll
            for (int mi = 0; mi < 4; mi++)
#pragma unroll
                for (int ni = 0; ni < 4; ni++)
                    mma_f16(acc[mi][ni], af + mi*4, &bf[(ni >> 1)*4 + (ni & 1)*2]);
        }
        stg ^= 1;
    }

    // epilogue
#pragma unroll
    for (int mi = 0; mi < 4; mi++) {
        int mrow = m0 + wm + mi*16 + (lane >> 2);
#pragma unroll
        for (int half = 0; half < 2; half++) {
            int m = mrow + half * 8;
#pragma unroll
            for (int ni = 0; ni < 4; ni++) {
                int n = n0 + wn + ni*8 + (lane & 3)*2;
                float v0 = acc[mi][ni][half*2 + 0];
                float v1 = acc[mi][ni][half*2 + 1];
                if (MODE == 1) {
                    *(float2*)(C + (size_t)m * EE + n) = make_float2(v0, v1);
                } else {
                    int s = n >> 10, h = (n >> 6) & 15, d = n & 63;
                    int bidx = m >> 12, l = m & 4095;
                    float r0, r1;
                    if (s == 0) {
                        r0 = (v0 > 0.f ? v0 + 1.f : expf(v0)) * 0.125f;
                        r1 = (v1 > 0.f ? v1 + 1.f : expf(v1)) * 0.125f;
                    } else if (s == 1) {
                        r0 = (v0 > 0.f ? v0 + 1.f : expf(v0));
                        r1 = (v1 > 0.f ? v1 + 1.f : expf(v1));
                    } else {
                        r0 = v0; r1 = v1;
                    }
                    __half* dst = (s == 0) ? g_qh : (s == 1) ? g_kh : g_vh;
                    size_t off = ((size_t)(bidx*HH + h) * LL + l) * DH + d;
                    *(uint32_t*)(dst + off) = packh2(r0, r1);
                }
            }
        }
    }
}

// ---------------- per-chunk Gram via HMMA: G = K_c^T V_c (64x64, k=256), z = sum K_c ----------------
#define KP 144
#define CKV_K_O 0
#define CKV_V_O (256*KP)          // 36864
#define CKV_SMEM (2*256*KP)       // 73728

__global__ __launch_bounds__(128, 3)
void chunk_kv_kernel()
{
    const int c = blockIdx.x, h = blockIdx.y, b = blockIdx.z;
    const int bh = b * HH + h;
    const size_t tokbase = ((size_t)bh * LL + c * CH) * DH;
    const __half* kh = g_kh + tokbase;
    const __half* vh = g_vh + tokbase;

    extern __shared__ char sm[];
    const uint32_t sbase = smem_u32(sm);

    const int tid = threadIdx.x;
    const int w = tid >> 5;
    const int lane = tid & 31;
    const int g = lane >> 3, lr = lane & 7;
    const int ka_row  = ((g >> 1) << 3) + lr;
    const int ka_xtra = (g & 1) * 16;
    const int vt_row = lane & 15;
    const int vt_cb  = (lane >> 4) << 4;

#pragma unroll
    for (int t = 0; t < 16; t++) {
        int idx = tid + t * 128;
        int row = idx >> 3, c16 = idx & 7;
        uint32_t so = (uint32_t)(row * KP + c16 * 16);
        *(uint4*)(sm + CKV_K_O + so) = *(const uint4*)(kh + (size_t)row * DH + c16 * 8);
        *(uint4*)(sm + CKV_V_O + so) = *(const uint4*)(vh + (size_t)row * DH + c16 * 8);
    }
    __syncthreads();

    float acc[8][4];
#pragma unroll
    for (int ni = 0; ni < 8; ni++)
#pragma unroll
        for (int e = 0; e < 4; e++) acc[ni][e] = 0.f;

#pragma unroll
    for (int t = 0; t < 16; t++) {
        uint32_t af[4];
        ldmx4t(af, sbase + CKV_K_O + (uint32_t)((t*16 + ka_row) * KP + w*32 + ka_xtra));
        uint32_t vb[16];
#pragma unroll
        for (int np = 0; np < 4; np++)
            ldmx4t(vb + np*4, sbase + CKV_V_O + (uint32_t)((t*16 + vt_row) * KP + np*32 + vt_cb));
#pragma unroll
        for (int ni = 0; ni < 8; ni++)
            mma_f16(acc[ni], af, &vb[(ni >> 1)*4 + (ni & 1)*2]);
    }

    float* Gout = g_G + ((size_t)bh * NCH + c) * DH * DH;
#pragma unroll
    for (int half = 0; half < 2; half++) {
        int d = w*16 + (lane >> 2) + half*8;
#pragma unroll
        for (int ni = 0; ni < 8; ni++) {
            int e = ni*8 + (lane & 3)*2;
            *(float2*)(Gout + d*DH + e) =
                make_float2(acc[ni][half*2 + 0], acc[ni][half*2 + 1]);
        }
    }

    if (tid < DH) {
        float zacc = 0.f;
        const char* kp = sm + CKV_K_O + tid*2;
#pragma unroll 8
        for (int l = 0; l < 256; l++)
            zacc += __half2float(*(const __half*)(kp + l*KP));
        g_zc[((size_t)bh * NCH + c) * DH + tid] = zacc;
    }
}

// ---------------- exclusive prefix over chunks (coalesced both sides) ----------------
// grid (16, 32): y = bh. S stored [d][e] fp16 — no transpose, attn uses trans-ldmatrix.
__global__ __launch_bounds__(256)
void prefix_kernel()
{
    const int bh = blockIdx.y;
    const int idx = blockIdx.x * 256 + threadIdx.x;   // 0..4095 = d*64+e
    const size_t gb = (size_t)bh * NCH * DH * DH;

    float gv[NCH];
#pragma unroll
    for (int c = 0; c < NCH; c++)
        gv[c] = g_G[gb + (size_t)c * DH * DH + idx];

    float run = 0.f;
#pragma unroll
    for (int c = 0; c < NCH; c++) {
        g_Sh[gb + (size_t)c * DH * DH + idx] = __float2half_rn(run);
        run += gv[c];
    }

    if (blockIdx.x == 0 && threadIdx.x < DH) {
        const size_t zb = (size_t)bh * NCH * DH;
        float zv[NCH];
#pragma unroll
        for (int c = 0; c < NCH; c++)
            zv[c] = g_zc[zb + (size_t)c * DH + threadIdx.x];
        float zr = 0.f;
#pragma unroll
        for (int c = 0; c < NCH; c++) {
            g_Z[zb + (size_t)c * DH + threadIdx.x] = zr;
            zr += zv[c];
        }
    }
}

// ---------------- attention core (fp16 HMMA): per (b,h,c,rh), 128x64 tile ----------------
#define AP 144
#define QH_O  0
#define KH_O  18432
#define VH_O  27648
#define ST_O  36864
#define Z_O   46080
#define ATTN_SMEM (Z_O + 256)

__global__ __launch_bounds__(128, 3)
void attn_core_kernel()
{
    const int cc = blockIdx.x;
    const int c = cc >> 1, rh = cc & 1;
    const int h = blockIdx.y, b = blockIdx.z;
    const int bh = b * HH + h;
    const size_t tokbase = (size_t)bh * LL + c * CH;
    const int rowbase = rh * 128;

    extern __shared__ char sm[];
    const uint32_t sbase = smem_u32(sm);

    const int tid = threadIdx.x;
    const int w = tid >> 5;
    const int lane = tid & 31;
    const int g = lane >> 3, lr = lane & 7;
    const int a_row  = ((g & 1) << 3) + lr;
    const int a_xtra = (g & 2) ? 16 : 0;
    const int b_row  = ((g >> 1) << 3) + lr;
    const int b_xtra = (g & 1) ? 16 : 0;
    const int vt_row = lane & 15;
    const int vt_cb  = (lane >> 4) << 4;

    // load Q (128 rows x 64)
    {
        const __half* qh = g_qh + (tokbase + rowbase) * DH;
#pragma unroll
        for (int t = 0; t < 8; t++) {
            int idx = tid + t * 128;
            int row = idx >> 3, c16 = idx & 7;
            *(uint4*)(sm + QH_O + row*AP + c16*16) = *(const uint4*)(qh + (size_t)row*DH + c16*8);
        }
    }
    // load S ([d][e], 64x64) + Z
    {
        const size_t stb = ((size_t)bh * NCH + c) * DH * DH;
#pragma unroll
        for (int t = 0; t < 4; t++) {
            int idx = tid + t * 128;
            int row = idx >> 3, c16 = idx & 7;
            *(uint4*)(sm + ST_O + row*AP + c16*16) = *(const uint4*)(g_Sh + stb + (size_t)row*DH + c16*8);
        }
        if (tid < DH) *(float*)(sm + Z_O + tid*4) = g_Z[((size_t)bh * NCH + c) * DH + tid];
    }

    float num[2][8][4];
#pragma unroll
    for (int mi = 0; mi < 2; mi++)
#pragma unroll
        for (int ni = 0; ni < 8; ni++)
#pragma unroll
            for (int e = 0; e < 4; e++) num[mi][ni][e] = 0.f;
    float den[2][2] = {{0.f, 0.f}, {0.f, 0.f}};

    const int jb_max = rh * 2 + 2;
    for (int jb = 0; jb < jb_max; jb++) {
        __syncthreads();
        {
            const __half* kh = g_kh + (tokbase + jb*64) * DH;
            const __half* vh = g_vh + (tokbase + jb*64) * DH;
#pragma unroll
            for (int t = 0; t < 4; t++) {
                int idx = tid + t * 128;
                int row = idx >> 3, c16 = idx & 7;
                *(uint4*)(sm + KH_O + row*AP + c16*16) = *(const uint4*)(kh + (size_t)row*DH + c16*8);
                *(uint4*)(sm + VH_O + row*AP + c16*16) = *(const uint4*)(vh + (size_t)row*DH + c16*8);
            }
        }
        __syncthreads();

        // GEMM1: P = Q_half * Kstrip^T
        float pacc[2][8][4];
#pragma unroll
        for (int mi = 0; mi < 2; mi++)
#pragma unroll
            for (int ni = 0; ni < 8; ni++)
#pragma unroll
                for (int e = 0; e < 4; e++) pacc[mi][ni][e] = 0.f;

#pragma unroll
        for (int t = 0; t < 4; t++) {
            uint32_t kb[16];
#pragma unroll
            for (int np = 0; np < 4; np++)
                ldmx4(kb + np*4, sbase + KH_O + (uint32_t)((np*16 + b_row)*AP + t*32 + b_xtra));
#pragma unroll
            for (int mi = 0; mi < 2; mi++) {
                uint32_t ah[4];
                ldmx4(ah, sbase + QH_O + (uint32_t)((w*32 + mi*16 + a_row)*AP + t*32 + a_xtra));
#pragma unroll
                for (int ni = 0; ni < 8; ni++)
                    mma_f16(pacc[mi][ni], ah, &kb[(ni >> 1)*4 + (ni & 1)*2]);
            }
        }

        // causal mask + den partials
#pragma unroll
        for (int mi = 0; mi < 2; mi++)
#pragma unroll
            for (int ni = 0; ni < 8; ni++)
#pragma unroll
                for (int e = 0; e < 4; e++) {
                    int row = rowbase + w*32 + mi*16 + (lane >> 2) + (e >> 1)*8;
                    int col = jb*64 + ni*8 + (lane & 3)*2 + (e & 1);
                    if (col > row) pacc[mi][ni][e] = 0.f;
                    else           den[mi][e >> 1] += pacc[mi][ni][e];
                }

        // GEMM2: num += P * Vstrip
#pragma unroll
        for (int t = 0; t < 4; t++) {
            uint32_t vb[16];
#pragma unroll
            for (int np = 0; np < 4; np++)
                ldmx4t(vb + np*4, sbase + VH_O +
                       (uint32_t)((t*16 + vt_row)*AP + np*32 + vt_cb));
#pragma unroll
            for (int mi = 0; mi < 2; mi++) {
                uint32_t ph[4];
                ph[0] = packh2(pacc[mi][2*t][0],   pacc[mi][2*t][1]);
                ph[1] = packh2(pacc[mi][2*t][2],   pacc[mi][2*t][3]);
                ph[2] = packh2(pacc[mi][2*t+1][0], pacc[mi][2*t+1][1]);
                ph[3] = packh2(pacc[mi][2*t+1][2], pacc[mi][2*t+1][3]);
#pragma unroll
                for (int ni = 0; ni < 8; ni++)
                    mma_f16(num[mi][ni], ph, &vb[(ni >> 1)*4 + (ni & 1)*2]);
            }
        }
    }

    // inter-chunk: num += Q * S  (S stored [d][e] -> B-fragments via trans-ldmatrix)
#pragma unroll
    for (int t = 0; t < 4; t++) {
        uint32_t sb[16];
#pragma unroll
        for (int np = 0; np < 4; np++)
            ldmx4t(sb + np*4, sbase + ST_O +
                   (uint32_t)((t*16 + vt_row)*AP + np*32 + vt_cb));
#pragma unroll
        for (int mi = 0; mi < 2; mi++) {
            uint32_t ah[4];
            ldmx4(ah, sbase + QH_O + (uint32_t)((w*32 + mi*16 + a_row)*AP + t*32 + a_xtra));
#pragma unroll
            for (int ni = 0; ni < 8; ni++)
                mma_f16(num[mi][ni], ah, &sb[(ni >> 1)*4 + (ni & 1)*2]);
        }
    }

    // den: quad reduce, then + q.Z
#pragma unroll
    for (int mi = 0; mi < 2; mi++)
#pragma unroll
        for (int hf = 0; hf < 2; hf++) {
            float d = den[mi][hf];
            d += __shfl_xor_sync(0xffffffffu, d, 1);
            d += __shfl_xor_sync(0xffffffffu, d, 2);
            int row = w*32 + mi*16 + (lane >> 2) + hf*8;
            float qz = 0.f;
            const char* qr = sm + QH_O + row*AP;
#pragma unroll
            for (int dd = 0; dd < 32; dd++) {
                float2 q2 = __half22float2(*(const __half2*)(qr + dd*4));
                float2 z2 = *(const float2*)(sm + Z_O + dd*8);
                qz += q2.x * z2.x + q2.y * z2.y;
            }
            den[mi][hf] = d + qz;
        }

    // divide + fp16 store
    const size_t mbase = (size_t)(b * LL + c * CH) + rowbase;
#pragma unroll
    for (int mi = 0; mi < 2; mi++)
#pragma unroll
        for (int hf = 0; hf < 2; hf++) {
            int row = w*32 + mi*16 + (lane >> 2) + hf*8;
            float inv = 1.f / fmaxf(den[mi][hf], 1e-6f);
            size_t ob = (mbase + row) * EE + h * DH;
#pragma unroll
            for (int ni = 0; ni < 8; ni++) {
                int e = ni*8 + (lane & 3)*2;
                *(uint32_t*)(g_atth + ob + e) =
                    packh2(num[mi][ni][hf*2 + 0] * inv, num[mi][ni][hf*2 + 1] * inv);
            }
        }
}

// ---------------- launch ----------------
extern "C" void kernel_launch(void* const* d_in, const int* in_sizes, int n_in,
                              void* d_out, int out_size)
{
    const float* x    = (const float*)d_in[0];   // [B, L, E]
    const float* Wqkv = (const float*)d_in[1];   // [3E, E]
    const float* Wout = (const float*)d_in[2];   // [E, E]
    float* out = (float*)d_out;                  // [B, L, E]

    cudaFuncSetAttribute(attn_core_kernel,
                         cudaFuncAttributeMaxDynamicSharedMemorySize, ATTN_SMEM);
    cudaFuncSetAttribute(chunk_kv_kernel,
                         cudaFuncAttributeMaxDynamicSharedMemorySize, CKV_SMEM);
    cudaFuncSetAttribute(hmma_gemm_kernel<0>,
                         cudaFuncAttributeMaxDynamicSharedMemorySize, GSMEM);
    cudaFuncSetAttribute(hmma_gemm_kernel<1>,
                         cudaFuncAttributeMaxDynamicSharedMemorySize, GSMEM);

    // 0) fp16 conversion of all inputs (one launch)
    convert_all_kernel<<<(N4_TOT + 255)/256, 256>>>(x, Wqkv, Wout);

    // 1) QKV GEMM + feature-map -> fp16 q/k/v
    {
        dim3 grid(NQKV/128, M1/128);  // (24, 64)
        hmma_gemm_kernel<0><<<grid, 256, GSMEM>>>(nullptr);
    }
    // 2) per-chunk Gram matrices (HMMA)
    {
        dim3 grid(NCH, HH, BB);
        chunk_kv_kernel<<<grid, 128, CKV_SMEM>>>();
    }
    // 3) exclusive prefix (coalesced, S kept [d][e])
    {
        dim3 grid(DH*DH/256, BB*HH);  // (16, 32)
        prefix_kernel<<<grid, 256>>>();
    }
    // 4) attention core (fp16 HMMA, 128-row half-tiles, causal strip-skip)
    {
        dim3 grid(NCH*2, HH, BB);
        attn_core_kernel<<<grid, 128, ATTN_SMEM>>>();
    }
    // 5) output GEMM: out = att @ Wout^T
    {
        dim3 grid(EE/128, M1/128);    // (8, 64)
        hmma_gemm_kernel<1><<<grid, 256, GSMEM>>>(out);
    }
}